// round 1
// baseline (speedup 1.0000x reference)
#include <cuda_runtime.h>

#define B_NODES 16384
#define L_HIST  50
#define D       64
#define NI      100000
#define NR      5
#define LDP     68      // padded leading dim for transposed activation buffers

// Scratch (module-static device memory; allocation-free at launch time)
__device__ float g_h_pre[NI * D];     // v2e_w @ W1_top   (25.6 MB, lives in L2)
__device__ float g_r_pre[NR * D];     // r2e_w @ W1_bot + b1

// ---------------------------------------------------------------------------
// Precompute r_pre: [5,64]
// ---------------------------------------------------------------------------
__global__ void pre_r_kernel(const float* __restrict__ r2e,
                             const float* __restrict__ w1,
                             const float* __restrict__ b1)
{
    int t = threadIdx.x;
    if (t < NR * D) {
        int r = t / D, j = t % D;
        float acc = b1[j];
        #pragma unroll 16
        for (int k = 0; k < D; k++)
            acc = fmaf(r2e[r * D + k], w1[(D + k) * D + j], acc);
        g_r_pre[t] = acc;
    }
}

// ---------------------------------------------------------------------------
// Precompute h_pre[i,:] = v2e_w[i,:] @ W1_top  (block = 16 rows, 256 threads)
// ---------------------------------------------------------------------------
__global__ void __launch_bounds__(256)
pre_h_kernel(const float* __restrict__ v2e,
             const float* __restrict__ w1)
{
    __shared__ float W1s[D * D];
    __shared__ float As[16 * D];
    int t = threadIdx.x;
    int base = blockIdx.x * 16;

    for (int i = t; i < D * D; i += 256) W1s[i] = w1[i];          // top half rows 0..63
    for (int i = t; i < 16 * D; i += 256) As[i] = v2e[base * D + i];
    __syncthreads();

    int tx = t & 15, ty = t >> 4;   // row = base+ty, cols 4*tx..4*tx+3
    float4 acc = make_float4(0.f, 0.f, 0.f, 0.f);
    #pragma unroll
    for (int k = 0; k < D; k++) {
        float a = As[ty * D + k];
        float4 b = *(const float4*)&W1s[k * D + 4 * tx];
        acc.x = fmaf(a, b.x, acc.x);
        acc.y = fmaf(a, b.y, acc.y);
        acc.z = fmaf(a, b.z, acc.z);
        acc.w = fmaf(a, b.w, acc.w);
    }
    *(float4*)&g_h_pre[(base + ty) * D + 4 * tx] = acc;
}

// ---------------------------------------------------------------------------
// Main persistent kernel
// ---------------------------------------------------------------------------
struct __align__(16) Smem {
    float W2s[D * D];       // w_r2_w
    float A1t[D * D];       // att1_w rows 0..63   (o part)
    float A1b[D * D];       // att1_w rows 64..127 (uv part)
    float A2s[D * D];       // att2_w
    float Ht[D * LDP];      // transposed activations [feature][l]
    float Ot[D * LDP];      // transposed o          [feature][l]
    float a3s[D];
    float b_r2[D];
    float b_a1[D];
    float b_a2[D];
    float rpre[NR * D];
    float uvs[D];
    float u_att[D];
    float logits[D];
    float attw[D];
    float b_a3;
    int   items[L_HIST];
    int   rats[L_HIST];
};

__global__ void __launch_bounds__(256, 2)
uv_agg_main(const int* __restrict__ nodes,
            const int* __restrict__ huv,
            const int* __restrict__ hr,
            const float* __restrict__ u2e,
            const float* __restrict__ w2w, const float* __restrict__ w2b,
            const float* __restrict__ a1w, const float* __restrict__ a1b,
            const float* __restrict__ a2w, const float* __restrict__ a2b,
            const float* __restrict__ a3w, const float* __restrict__ a3b,
            float* __restrict__ out)
{
    extern __shared__ __align__(16) char sraw[];
    Smem& s = *reinterpret_cast<Smem*>(sraw);
    const int t  = threadIdx.x;
    const int tx = t & 15;          // col group: j = 4*tx .. 4*tx+3
    const int ty = t >> 4;          // row group: l = 4*ty .. 4*ty+3

    // One-time weight staging per block
    for (int i = t; i < D * D; i += 256) {
        s.W2s[i] = w2w[i];
        s.A1t[i] = a1w[i];
        s.A1b[i] = a1w[D * D + i];
        s.A2s[i] = a2w[i];
    }
    if (t < D) {
        s.a3s[t]  = a3w[t];
        s.b_r2[t] = w2b[t];
        s.b_a1[t] = a1b[t];
        s.b_a2[t] = a2b[t];
    }
    for (int i = t; i < NR * D; i += 256) s.rpre[i] = g_r_pre[i];
    if (t == 0) s.b_a3 = a3b[0];
    __syncthreads();

    for (int b = blockIdx.x; b < B_NODES; b += gridDim.x) {
        // ---- gather indices + uv embedding ----
        if (t < L_HIST) {
            s.items[t] = huv[b * L_HIST + t];
            s.rats[t]  = hr[b * L_HIST + t];
        }
        if (t >= 64 && t < 128) {
            int node = nodes[b];
            s.uvs[t - 64] = u2e[node * D + (t - 64)];
        }
        __syncthreads();

        // ---- Ht[j][l] = relu(h_pre[item_l][j] + r_pre[r_l][j]), zero-pad l>=50 ----
        for (int idx = t; idx < D * D; idx += 256) {
            int l = idx >> 6, j = idx & 63;
            float v = 0.f;
            if (l < L_HIST) {
                float hp = g_h_pre[s.items[l] * D + j];
                float rp = s.rpre[s.rats[l] * D + j];
                v = fmaxf(hp + rp, 0.f);
            }
            s.Ht[j * LDP + l] = v;
        }
        // ---- per-node uv half of att1: u_att[j] = uv @ A1b[:,j] + b_a1[j] ----
        if (t < D) {
            float acc = s.b_a1[t];
            #pragma unroll 16
            for (int k = 0; k < D; k++)
                acc = fmaf(s.uvs[k], s.A1b[k * D + t], acc);
            s.u_att[t] = acc;
        }
        __syncthreads();

        float acc[4][4];

        // ================= GEMM A: O = relu(H @ W2 + b_r2) =================
        #pragma unroll
        for (int r = 0; r < 4; r++)
            #pragma unroll
            for (int c = 0; c < 4; c++) acc[r][c] = s.b_r2[4 * tx + c];
        #pragma unroll
        for (int k = 0; k < D; k++) {
            float4 a = *(const float4*)&s.Ht[k * LDP + 4 * ty];
            float4 w = *(const float4*)&s.W2s[k * D + 4 * tx];
            acc[0][0]=fmaf(a.x,w.x,acc[0][0]); acc[0][1]=fmaf(a.x,w.y,acc[0][1]);
            acc[0][2]=fmaf(a.x,w.z,acc[0][2]); acc[0][3]=fmaf(a.x,w.w,acc[0][3]);
            acc[1][0]=fmaf(a.y,w.x,acc[1][0]); acc[1][1]=fmaf(a.y,w.y,acc[1][1]);
            acc[1][2]=fmaf(a.y,w.z,acc[1][2]); acc[1][3]=fmaf(a.y,w.w,acc[1][3]);
            acc[2][0]=fmaf(a.z,w.x,acc[2][0]); acc[2][1]=fmaf(a.z,w.y,acc[2][1]);
            acc[2][2]=fmaf(a.z,w.z,acc[2][2]); acc[2][3]=fmaf(a.z,w.w,acc[2][3]);
            acc[3][0]=fmaf(a.w,w.x,acc[3][0]); acc[3][1]=fmaf(a.w,w.y,acc[3][1]);
            acc[3][2]=fmaf(a.w,w.z,acc[3][2]); acc[3][3]=fmaf(a.w,w.w,acc[3][3]);
        }
        #pragma unroll
        for (int c = 0; c < 4; c++) {
            float4 v;
            v.x = fmaxf(acc[0][c], 0.f);
            v.y = fmaxf(acc[1][c], 0.f);
            v.z = fmaxf(acc[2][c], 0.f);
            v.w = fmaxf(acc[3][c], 0.f);
            *(float4*)&s.Ot[(4 * tx + c) * LDP + 4 * ty] = v;
        }
        __syncthreads();

        // ============ GEMM B: a1 = relu(O @ A1t + u_att) -> Ht =============
        #pragma unroll
        for (int r = 0; r < 4; r++)
            #pragma unroll
            for (int c = 0; c < 4; c++) acc[r][c] = s.u_att[4 * tx + c];
        #pragma unroll
        for (int k = 0; k < D; k++) {
            float4 a = *(const float4*)&s.Ot[k * LDP + 4 * ty];
            float4 w = *(const float4*)&s.A1t[k * D + 4 * tx];
            acc[0][0]=fmaf(a.x,w.x,acc[0][0]); acc[0][1]=fmaf(a.x,w.y,acc[0][1]);
            acc[0][2]=fmaf(a.x,w.z,acc[0][2]); acc[0][3]=fmaf(a.x,w.w,acc[0][3]);
            acc[1][0]=fmaf(a.y,w.x,acc[1][0]); acc[1][1]=fmaf(a.y,w.y,acc[1][1]);
            acc[1][2]=fmaf(a.y,w.z,acc[1][2]); acc[1][3]=fmaf(a.y,w.w,acc[1][3]);
            acc[2][0]=fmaf(a.z,w.x,acc[2][0]); acc[2][1]=fmaf(a.z,w.y,acc[2][1]);
            acc[2][2]=fmaf(a.z,w.z,acc[2][2]); acc[2][3]=fmaf(a.z,w.w,acc[2][3]);
            acc[3][0]=fmaf(a.w,w.x,acc[3][0]); acc[3][1]=fmaf(a.w,w.y,acc[3][1]);
            acc[3][2]=fmaf(a.w,w.z,acc[3][2]); acc[3][3]=fmaf(a.w,w.w,acc[3][3]);
        }
        __syncthreads();   // Ht free to overwrite (GEMM A consumed it)
        #pragma unroll
        for (int c = 0; c < 4; c++) {
            float4 v;
            v.x = fmaxf(acc[0][c], 0.f);
            v.y = fmaxf(acc[1][c], 0.f);
            v.z = fmaxf(acc[2][c], 0.f);
            v.w = fmaxf(acc[3][c], 0.f);
            *(float4*)&s.Ht[(4 * tx + c) * LDP + 4 * ty] = v;
        }
        __syncthreads();

        // ===== GEMM C: a2 = relu(a1 @ A2 + b_a2); logits = a2 @ a3 + b3 ====
        #pragma unroll
        for (int r = 0; r < 4; r++)
            #pragma unroll
            for (int c = 0; c < 4; c++) acc[r][c] = s.b_a2[4 * tx + c];
        #pragma unroll
        for (int k = 0; k < D; k++) {
            float4 a = *(const float4*)&s.Ht[k * LDP + 4 * ty];
            float4 w = *(const float4*)&s.A2s[k * D + 4 * tx];
            acc[0][0]=fmaf(a.x,w.x,acc[0][0]); acc[0][1]=fmaf(a.x,w.y,acc[0][1]);
            acc[0][2]=fmaf(a.x,w.z,acc[0][2]); acc[0][3]=fmaf(a.x,w.w,acc[0][3]);
            acc[1][0]=fmaf(a.y,w.x,acc[1][0]); acc[1][1]=fmaf(a.y,w.y,acc[1][1]);
            acc[1][2]=fmaf(a.y,w.z,acc[1][2]); acc[1][3]=fmaf(a.y,w.w,acc[1][3]);
            acc[2][0]=fmaf(a.z,w.x,acc[2][0]); acc[2][1]=fmaf(a.z,w.y,acc[2][1]);
            acc[2][2]=fmaf(a.z,w.z,acc[2][2]); acc[2][3]=fmaf(a.z,w.w,acc[2][3]);
            acc[3][0]=fmaf(a.w,w.x,acc[3][0]); acc[3][1]=fmaf(a.w,w.y,acc[3][1]);
            acc[3][2]=fmaf(a.w,w.z,acc[3][2]); acc[3][3]=fmaf(a.w,w.w,acc[3][3]);
        }
        float plog[4];
        #pragma unroll
        for (int r = 0; r < 4; r++) {
            float p = 0.f;
            #pragma unroll
            for (int c = 0; c < 4; c++)
                p = fmaf(fmaxf(acc[r][c], 0.f), s.a3s[4 * tx + c], p);
            plog[r] = p;
        }
        // butterfly-reduce over the 16 tx lanes (stays within each half-warp)
        #pragma unroll
        for (int off = 8; off >= 1; off >>= 1) {
            #pragma unroll
            for (int r = 0; r < 4; r++)
                plog[r] += __shfl_xor_sync(0xffffffffu, plog[r], off);
        }
        if (tx == 0) {
            #pragma unroll
            for (int r = 0; r < 4; r++)
                s.logits[4 * ty + r] = s.b_a3 + plog[r];
        }
        __syncthreads();

        // ---- softmax over l in [0,50), warp 0 ----
        if (t < 32) {
            float v1 = s.logits[t];
            float v2 = (t + 32 < L_HIST) ? s.logits[t + 32] : -1e30f;
            float m = fmaxf(v1, v2);
            #pragma unroll
            for (int off = 16; off >= 1; off >>= 1)
                m = fmaxf(m, __shfl_xor_sync(0xffffffffu, m, off));
            float e1 = __expf(v1 - m);
            float e2 = (t + 32 < L_HIST) ? __expf(v2 - m) : 0.f;
            float ssum = e1 + e2;
            #pragma unroll
            for (int off = 16; off >= 1; off >>= 1)
                ssum += __shfl_xor_sync(0xffffffffu, ssum, off);
            float inv = 1.f / ssum;
            s.attw[t] = e1 * inv;
            if (t + 32 < L_HIST) s.attw[t + 32] = e2 * inv;
        }
        __syncthreads();

        // ---- out[b][j] = sum_l attw[l] * o[l][j] (Ot holds o transposed) ----
        if (t < D) {
            float acc2 = 0.f;
            #pragma unroll
            for (int l = 0; l < L_HIST; l++)
                acc2 = fmaf(s.attw[l], s.Ot[t * LDP + l], acc2);
            out[b * D + t] = acc2;
        }
        __syncthreads();   // protect smem before next node iteration
    }
}

// ---------------------------------------------------------------------------
extern "C" void kernel_launch(void* const* d_in, const int* in_sizes, int n_in,
                              void* d_out, int out_size)
{
    const int*   nodes = (const int*)d_in[0];
    const int*   huv   = (const int*)d_in[1];
    const int*   hr    = (const int*)d_in[2];
    const float* v2e   = (const float*)d_in[3];
    const float* u2e   = (const float*)d_in[4];
    const float* r2e   = (const float*)d_in[5];
    const float* w1w   = (const float*)d_in[6];
    const float* w1b   = (const float*)d_in[7];
    const float* w2w   = (const float*)d_in[8];
    const float* w2b   = (const float*)d_in[9];
    const float* a1w   = (const float*)d_in[10];
    const float* a1b   = (const float*)d_in[11];
    const float* a2w   = (const float*)d_in[12];
    const float* a2b   = (const float*)d_in[13];
    const float* a3w   = (const float*)d_in[14];
    const float* a3b   = (const float*)d_in[15];
    float* out = (float*)d_out;

    (void)in_sizes; (void)n_in; (void)out_size;

    // opt in to >48KB dynamic smem (idempotent; not a stream op)
    cudaFuncSetAttribute(uv_agg_main,
                         cudaFuncAttributeMaxDynamicSharedMemorySize,
                         (int)sizeof(Smem));

    pre_r_kernel<<<1, NR * D>>>(r2e, w1w, w1b);
    pre_h_kernel<<<NI / 16, 256>>>(v2e, w1w);
    uv_agg_main<<<296, 256, sizeof(Smem)>>>(nodes, huv, hr, u2e,
                                            w2w, w2b, a1w, a1b,
                                            a2w, a2b, a3w, a3b, out);
}

// round 2
// speedup vs baseline: 1.9750x; 1.9750x over previous
#include <cuda_runtime.h>
#include <cstdint>

#define B_NODES 16384
#define L_HIST  50
#define D       64
#define NI      100000
#define NR      5
#define LDH     68      // padded leading dim (floats) for all 64-col smem matrices

// Scratch (module-static device memory; allocation-free at launch time)
__device__ float g_h_pre[NI * D];     // v2e_w @ W1_top   (25.6 MB, lives in L2)
__device__ float g_r_pre[NR * D];     // r2e_w @ W1_bot + b1

// ---------------------------------------------------------------------------
// Precompute r_pre: [5,64]
// ---------------------------------------------------------------------------
__global__ void pre_r_kernel(const float* __restrict__ r2e,
                             const float* __restrict__ w1,
                             const float* __restrict__ b1)
{
    int t = threadIdx.x;
    if (t < NR * D) {
        int r = t / D, j = t % D;
        float acc = b1[j];
        #pragma unroll 16
        for (int k = 0; k < D; k++)
            acc = fmaf(r2e[r * D + k], w1[(D + k) * D + j], acc);
        g_r_pre[t] = acc;
    }
}

// ---------------------------------------------------------------------------
// Precompute h_pre[i,:] = v2e_w[i,:] @ W1_top  (block = 16 rows, 256 threads)
// ---------------------------------------------------------------------------
__global__ void __launch_bounds__(256)
pre_h_kernel(const float* __restrict__ v2e,
             const float* __restrict__ w1)
{
    __shared__ float W1s[D * D];
    __shared__ float As[16 * D];
    int t = threadIdx.x;
    int base = blockIdx.x * 16;

    for (int i = t; i < D * D; i += 256) W1s[i] = w1[i];          // top half rows 0..63
    for (int i = t; i < 16 * D; i += 256) As[i] = v2e[base * D + i];
    __syncthreads();

    int tx = t & 15, ty = t >> 4;
    float4 acc = make_float4(0.f, 0.f, 0.f, 0.f);
    #pragma unroll
    for (int k = 0; k < D; k++) {
        float a = As[ty * D + k];
        float4 b = *(const float4*)&W1s[k * D + 4 * tx];
        acc.x = fmaf(a, b.x, acc.x);
        acc.y = fmaf(a, b.y, acc.y);
        acc.z = fmaf(a, b.z, acc.z);
        acc.w = fmaf(a, b.w, acc.w);
    }
    *(float4*)&g_h_pre[(base + ty) * D + 4 * tx] = acc;
}

// ---------------------------------------------------------------------------
// tf32 helpers
// ---------------------------------------------------------------------------
__device__ __forceinline__ uint32_t f2tf32(float f) {
    uint32_t u;
    asm("cvt.rna.tf32.f32 %0, %1;" : "=r"(u) : "f"(f));
    return u;
}

__device__ __forceinline__ void mma_tf32(float (&d)[4],
                                         const uint32_t (&a)[4],
                                         const uint32_t (&b)[2])
{
    asm volatile(
        "mma.sync.aligned.m16n8k8.row.col.f32.tf32.tf32.f32 "
        "{%0,%1,%2,%3}, {%4,%5,%6,%7}, {%8,%9}, {%0,%1,%2,%3};\n"
        : "+f"(d[0]), "+f"(d[1]), "+f"(d[2]), "+f"(d[3])
        : "r"(a[0]), "r"(a[1]), "r"(a[2]), "r"(a[3]), "r"(b[0]), "r"(b[1]));
}

// One 64x64x64 GEMM: acc = bias ; acc += A(tf32,[64][LDH]) @ W(tf32,[64][LDH])
// Warp tile: 32 rows x 16 cols (2 m-tiles x 2 n-tiles of m16n8k8).
__device__ __forceinline__ void run_mma_gemm(
    const uint32_t* __restrict__ Abuf, const uint32_t* __restrict__ Wbuf,
    const float* __restrict__ bias, float (&acc)[2][2][4],
    int mb, int nb, int g, int q)
{
    #pragma unroll
    for (int mt = 0; mt < 2; mt++)
        #pragma unroll
        for (int nt = 0; nt < 2; nt++) {
            int c = nb + 8 * nt + 2 * q;
            float b0 = bias[c], b1 = bias[c + 1];
            acc[mt][nt][0] = b0; acc[mt][nt][1] = b1;
            acc[mt][nt][2] = b0; acc[mt][nt][3] = b1;
        }
    #pragma unroll
    for (int ks = 0; ks < 8; ks++) {
        const int kb = ks * 8;
        uint32_t a[2][4], bb[2][2];
        #pragma unroll
        for (int mt = 0; mt < 2; mt++) {
            const uint32_t* ap = Abuf + (mb + 16 * mt + g) * LDH + kb + q;
            a[mt][0] = ap[0];
            a[mt][1] = ap[8 * LDH];
            a[mt][2] = ap[4];
            a[mt][3] = ap[8 * LDH + 4];
        }
        #pragma unroll
        for (int nt = 0; nt < 2; nt++) {
            const uint32_t* bp = Wbuf + (kb + q) * LDH + nb + 8 * nt + g;
            bb[nt][0] = bp[0];
            bb[nt][1] = bp[4 * LDH];
        }
        #pragma unroll
        for (int mt = 0; mt < 2; mt++)
            #pragma unroll
            for (int nt = 0; nt < 2; nt++)
                mma_tf32(acc[mt][nt], a[mt], bb[nt]);
    }
}

// relu + tf32-convert + store the 32x16 warp tile into Out[64][LDH]
__device__ __forceinline__ void store_relu_tf32(
    uint32_t* __restrict__ Out, float (&acc)[2][2][4],
    int mb, int nb, int g, int q)
{
    #pragma unroll
    for (int mt = 0; mt < 2; mt++)
        #pragma unroll
        for (int nt = 0; nt < 2; nt++) {
            int r0 = mb + 16 * mt + g;
            int c  = nb + 8 * nt + 2 * q;
            uint2 v0, v1;
            v0.x = f2tf32(fmaxf(acc[mt][nt][0], 0.f));
            v0.y = f2tf32(fmaxf(acc[mt][nt][1], 0.f));
            v1.x = f2tf32(fmaxf(acc[mt][nt][2], 0.f));
            v1.y = f2tf32(fmaxf(acc[mt][nt][3], 0.f));
            *(uint2*)(Out + r0 * LDH + c)       = v0;
            *(uint2*)(Out + (r0 + 8) * LDH + c) = v1;
        }
}

// ---------------------------------------------------------------------------
// Main persistent kernel
// ---------------------------------------------------------------------------
struct __align__(16) Smem {
    uint32_t W2s[D * LDH];    // w_r2_w  (tf32 bits)
    uint32_t A1ts[D * LDH];   // att1_w rows 0..63  (tf32 bits)
    uint32_t A2s[D * LDH];    // att2_w (tf32 bits)
    uint32_t Hbuf[D * LDH];   // activations (tf32 bits), row-major [l][k]
    uint32_t Obuf[D * LDH];   // o_history (tf32 bits), row-major [l][j]
    float A1b[D * D];         // att1_w rows 64..127 (f32, for u_att)
    float rpre[NR * D];
    float a3s[D];
    float b_r2[D];
    float b_a1[D];
    float b_a2[D];
    float uvs[D];
    float u_att[D];
    float lpart[D * 4];       // per-row logit partials, one slot per n-warp
    float logits[D];
    float attw[D];
    float b_a3;
    int   items[L_HIST];
    int   rats[L_HIST];
};

__global__ void __launch_bounds__(256, 2)
uv_agg_main(const int* __restrict__ nodes,
            const int* __restrict__ huv,
            const int* __restrict__ hr,
            const float* __restrict__ u2e,
            const float* __restrict__ w2w, const float* __restrict__ w2b,
            const float* __restrict__ a1w, const float* __restrict__ a1b,
            const float* __restrict__ a2w, const float* __restrict__ a2b,
            const float* __restrict__ a3w, const float* __restrict__ a3b,
            float* __restrict__ out)
{
    extern __shared__ __align__(16) char sraw[];
    Smem& s = *reinterpret_cast<Smem*>(sraw);
    const int t    = threadIdx.x;
    const int wid  = t >> 5;
    const int lane = t & 31;
    const int g    = lane >> 2;     // group id (0..7)
    const int q    = lane & 3;      // thread-in-group (0..3)
    const int mb   = (wid >> 2) * 32;   // warp row-block (0 or 32)
    const int nb   = (wid & 3) * 16;    // warp col-block (0,16,32,48)

    // One-time weight staging per block (convert to tf32)
    for (int i = t; i < D * D; i += 256) {
        int k = i >> 6, j = i & 63;
        s.W2s [k * LDH + j] = f2tf32(w2w[i]);
        s.A1ts[k * LDH + j] = f2tf32(a1w[i]);
        s.A2s [k * LDH + j] = f2tf32(a2w[i]);
        s.A1b[i] = a1w[D * D + i];
    }
    if (t < D) {
        s.a3s[t]  = a3w[t];
        s.b_r2[t] = w2b[t];
        s.b_a1[t] = a1b[t];
        s.b_a2[t] = a2b[t];
    }
    for (int i = t; i < NR * D; i += 256) s.rpre[i] = g_r_pre[i];
    if (t == 0) s.b_a3 = a3b[0];
    __syncthreads();

    for (int b = blockIdx.x; b < B_NODES; b += gridDim.x) {
        // ---- gather indices + uv embedding ----
        if (t < L_HIST) {
            s.items[t] = huv[b * L_HIST + t];
            s.rats[t]  = hr[b * L_HIST + t];
        }
        if (t >= 64 && t < 128) {
            int node = nodes[b];
            s.uvs[t - 64] = u2e[node * D + (t - 64)];
        }
        __syncthreads();

        // ---- Hbuf[l][k] = tf32(relu(h_pre[item_l][k] + r_pre[r_l][k])) ----
        for (int idx = t; idx < 1024; idx += 256) {   // 64 rows x 16 float4s
            int l = idx >> 4, j4 = idx & 15;
            uint4 v = make_uint4(0u, 0u, 0u, 0u);
            if (l < L_HIST) {
                float4 hp = ((const float4*)(g_h_pre + s.items[l] * D))[j4];
                float4 rp = ((const float4*)(s.rpre + s.rats[l] * D))[j4];
                v.x = f2tf32(fmaxf(hp.x + rp.x, 0.f));
                v.y = f2tf32(fmaxf(hp.y + rp.y, 0.f));
                v.z = f2tf32(fmaxf(hp.z + rp.z, 0.f));
                v.w = f2tf32(fmaxf(hp.w + rp.w, 0.f));
            }
            *(uint4*)(s.Hbuf + l * LDH + 4 * j4) = v;
        }
        // ---- u_att[j] = uv @ A1b[:,j] + b_a1[j] (f32) ----
        if (t < D) {
            float acc = s.b_a1[t];
            #pragma unroll 16
            for (int k = 0; k < D; k++)
                acc = fmaf(s.uvs[k], s.A1b[k * D + t], acc);
            s.u_att[t] = acc;
        }
        __syncthreads();

        float acc[2][2][4];

        // GEMM A: O = relu(H @ W2 + b_r2)
        run_mma_gemm(s.Hbuf, s.W2s, s.b_r2, acc, mb, nb, g, q);
        store_relu_tf32(s.Obuf, acc, mb, nb, g, q);
        __syncthreads();

        // GEMM B: a1 = relu(O @ A1t + u_att)  -> Hbuf
        run_mma_gemm(s.Obuf, s.A1ts, s.u_att, acc, mb, nb, g, q);
        store_relu_tf32(s.Hbuf, acc, mb, nb, g, q);
        __syncthreads();

        // GEMM C: a2 = relu(a1 @ A2 + b_a2); logits = a2 @ a3 (+ b_a3)
        run_mma_gemm(s.Hbuf, s.A2s, s.b_a2, acc, mb, nb, g, q);
        {
            float p[2][2] = {{0.f, 0.f}, {0.f, 0.f}};
            #pragma unroll
            for (int mt = 0; mt < 2; mt++)
                #pragma unroll
                for (int nt = 0; nt < 2; nt++) {
                    int c = nb + 8 * nt + 2 * q;
                    float w0 = s.a3s[c], w1 = s.a3s[c + 1];
                    p[mt][0] = fmaf(fmaxf(acc[mt][nt][0], 0.f), w0, p[mt][0]);
                    p[mt][0] = fmaf(fmaxf(acc[mt][nt][1], 0.f), w1, p[mt][0]);
                    p[mt][1] = fmaf(fmaxf(acc[mt][nt][2], 0.f), w0, p[mt][1]);
                    p[mt][1] = fmaf(fmaxf(acc[mt][nt][3], 0.f), w1, p[mt][1]);
                }
            // reduce over the 4 q-lanes (covers this warp's 16 cols)
            #pragma unroll
            for (int off = 1; off <= 2; off <<= 1) {
                #pragma unroll
                for (int mt = 0; mt < 2; mt++) {
                    p[mt][0] += __shfl_xor_sync(0xffffffffu, p[mt][0], off);
                    p[mt][1] += __shfl_xor_sync(0xffffffffu, p[mt][1], off);
                }
            }
            if (q == 0) {
                #pragma unroll
                for (int mt = 0; mt < 2; mt++) {
                    s.lpart[(mb + 16 * mt + g) * 4 + (wid & 3)]     = p[mt][0];
                    s.lpart[(mb + 16 * mt + g + 8) * 4 + (wid & 3)] = p[mt][1];
                }
            }
        }
        __syncthreads();

        if (t < D) {
            s.logits[t] = s.b_a3 + s.lpart[t * 4 + 0] + s.lpart[t * 4 + 1]
                                 + s.lpart[t * 4 + 2] + s.lpart[t * 4 + 3];
        }
        __syncthreads();

        // ---- softmax over l in [0,50), warp 0 ----
        if (t < 32) {
            float v1 = s.logits[t];
            float v2 = (t + 32 < L_HIST) ? s.logits[t + 32] : -1e30f;
            float m = fmaxf(v1, v2);
            #pragma unroll
            for (int off = 16; off >= 1; off >>= 1)
                m = fmaxf(m, __shfl_xor_sync(0xffffffffu, m, off));
            float e1 = __expf(v1 - m);
            float e2 = (t + 32 < L_HIST) ? __expf(v2 - m) : 0.f;
            float ssum = e1 + e2;
            #pragma unroll
            for (int off = 16; off >= 1; off >>= 1)
                ssum += __shfl_xor_sync(0xffffffffu, ssum, off);
            float inv = 1.f / ssum;
            s.attw[t] = e1 * inv;
            if (t + 32 < L_HIST) s.attw[t + 32] = e2 * inv;
        }
        __syncthreads();

        // ---- out[b][j] = sum_l attw[l] * o[l][j] ----
        if (t < D) {
            float acc2 = 0.f;
            #pragma unroll
            for (int l = 0; l < L_HIST; l++)
                acc2 = fmaf(s.attw[l], __uint_as_float(s.Obuf[l * LDH + t]), acc2);
            out[b * D + t] = acc2;
        }
        __syncthreads();   // protect smem before next node iteration
    }
}

// ---------------------------------------------------------------------------
extern "C" void kernel_launch(void* const* d_in, const int* in_sizes, int n_in,
                              void* d_out, int out_size)
{
    const int*   nodes = (const int*)d_in[0];
    const int*   huv   = (const int*)d_in[1];
    const int*   hr    = (const int*)d_in[2];
    const float* v2e   = (const float*)d_in[3];
    const float* u2e   = (const float*)d_in[4];
    const float* r2e   = (const float*)d_in[5];
    const float* w1w   = (const float*)d_in[6];
    const float* w1b   = (const float*)d_in[7];
    const float* w2w   = (const float*)d_in[8];
    const float* w2b   = (const float*)d_in[9];
    const float* a1w   = (const float*)d_in[10];
    const float* a1b   = (const float*)d_in[11];
    const float* a2w   = (const float*)d_in[12];
    const float* a2b   = (const float*)d_in[13];
    const float* a3w   = (const float*)d_in[14];
    const float* a3b   = (const float*)d_in[15];
    float* out = (float*)d_out;

    (void)in_sizes; (void)n_in; (void)out_size;

    cudaFuncSetAttribute(uv_agg_main,
                         cudaFuncAttributeMaxDynamicSharedMemorySize,
                         (int)sizeof(Smem));

    pre_r_kernel<<<1, NR * D>>>(r2e, w1w, w1b);
    pre_h_kernel<<<NI / 16, 256>>>(v2e, w1w);
    uv_agg_main<<<296, 256, sizeof(Smem)>>>(nodes, huv, hr, u2e,
                                            w2w, w2b, a1w, a1b,
                                            a2w, a2b, a3w, a3b, out);
}

// round 4
// speedup vs baseline: 2.4470x; 1.2390x over previous
#include <cuda_runtime.h>
#include <cuda_fp16.h>
#include <cstdint>

#define B_NODES 16384
#define L_HIST  50
#define D       64
#define NI      100000
#define NR      5
#define LDW     72       // halves per row (144 B) for all f16 matrices
#define LDO     68       // floats per row for Of32

// Scratch (module-static device memory; allocation-free at launch time)
__device__ float g_h_pre[NI * D];     // v2e_w @ W1_top   (25.6 MB, lives in L2)
__device__ float g_r_pre[NR * D];     // r2e_w @ W1_bot + b1

// ---------------------------------------------------------------------------
// Precompute r_pre: [5,64]
// ---------------------------------------------------------------------------
__global__ void pre_r_kernel(const float* __restrict__ r2e,
                             const float* __restrict__ w1,
                             const float* __restrict__ b1)
{
    int t = threadIdx.x;
    if (t < NR * D) {
        int r = t / D, j = t % D;
        float acc = b1[j];
        #pragma unroll 16
        for (int k = 0; k < D; k++)
            acc = fmaf(r2e[r * D + k], w1[(D + k) * D + j], acc);
        g_r_pre[t] = acc;
    }
}

// ---------------------------------------------------------------------------
// Precompute h_pre[i,:] = v2e_w[i,:] @ W1_top  (block = 64 rows, 512 threads)
// ---------------------------------------------------------------------------
__global__ void __launch_bounds__(512)
pre_h_kernel(const float* __restrict__ v2e,
             const float* __restrict__ w1)
{
    __shared__ float W1s[D * D];
    __shared__ float As[64 * D];
    int t = threadIdx.x;
    int base = blockIdx.x * 64;
    int nrow = min(64, NI - base);

    for (int i = t; i < D * D; i += 512) W1s[i] = w1[i];
    for (int i = t; i < nrow * D; i += 512) As[i] = v2e[base * D + i];
    __syncthreads();

    int row = t >> 3, cg = (t & 7) * 8;
    if (row < nrow) {
        float4 a0 = make_float4(0.f, 0.f, 0.f, 0.f);
        float4 a1 = make_float4(0.f, 0.f, 0.f, 0.f);
        #pragma unroll
        for (int k = 0; k < D; k++) {
            float a = As[row * D + k];
            float4 b0 = *(const float4*)&W1s[k * D + cg];
            float4 b1 = *(const float4*)&W1s[k * D + cg + 4];
            a0.x = fmaf(a, b0.x, a0.x); a0.y = fmaf(a, b0.y, a0.y);
            a0.z = fmaf(a, b0.z, a0.z); a0.w = fmaf(a, b0.w, a0.w);
            a1.x = fmaf(a, b1.x, a1.x); a1.y = fmaf(a, b1.y, a1.y);
            a1.z = fmaf(a, b1.z, a1.z); a1.w = fmaf(a, b1.w, a1.w);
        }
        *(float4*)&g_h_pre[(base + row) * D + cg]     = a0;
        *(float4*)&g_h_pre[(base + row) * D + cg + 4] = a1;
    }
}

// ---------------------------------------------------------------------------
// fp16 mma helper: m16n8k16 row.col, f32 accumulate
// ---------------------------------------------------------------------------
__device__ __forceinline__ void mma_f16(float (&d)[4],
                                        const uint32_t (&a)[4],
                                        const uint32_t (&b)[2])
{
    asm volatile(
        "mma.sync.aligned.m16n8k16.row.col.f32.f16.f16.f32 "
        "{%0,%1,%2,%3}, {%4,%5,%6,%7}, {%8,%9}, {%0,%1,%2,%3};\n"
        : "+f"(d[0]), "+f"(d[1]), "+f"(d[2]), "+f"(d[3])
        : "r"(a[0]), "r"(a[1]), "r"(a[2]), "r"(a[3]), "r"(b[0]), "r"(b[1]));
}

// One 64x64x64 GEMM: acc = bias ; acc += A(f16,[64][LDW]) @ Wt(f16,[n][LDW])^T
// Warp tile: 32 rows x 16 cols (2 m-tiles x 2 n-tiles of m16n8k16).
__device__ __forceinline__ void run_mma_gemm(
    const __half* __restrict__ Ab, const __half* __restrict__ Wt,
    const float* __restrict__ bias, float (&acc)[2][2][4],
    int mb, int nb, int g, int q)
{
    #pragma unroll
    for (int mt = 0; mt < 2; mt++)
        #pragma unroll
        for (int nt = 0; nt < 2; nt++) {
            int c = nb + 8 * nt + 2 * q;
            float b0 = bias[c], b1 = bias[c + 1];
            acc[mt][nt][0] = b0; acc[mt][nt][1] = b1;
            acc[mt][nt][2] = b0; acc[mt][nt][3] = b1;
        }
    #pragma unroll
    for (int ks = 0; ks < 4; ks++) {
        const int kb = ks * 16;
        uint32_t a[2][4], bb[2][2];
        #pragma unroll
        for (int mt = 0; mt < 2; mt++) {
            const __half* ap = Ab + (mb + 16 * mt + g) * LDW + kb + 2 * q;
            a[mt][0] = *(const uint32_t*)(ap);
            a[mt][1] = *(const uint32_t*)(ap + 8 * LDW);
            a[mt][2] = *(const uint32_t*)(ap + 8);
            a[mt][3] = *(const uint32_t*)(ap + 8 * LDW + 8);
        }
        #pragma unroll
        for (int nt = 0; nt < 2; nt++) {
            const __half* bp = Wt + (nb + 8 * nt + g) * LDW + kb + 2 * q;
            bb[nt][0] = *(const uint32_t*)(bp);
            bb[nt][1] = *(const uint32_t*)(bp + 8);
        }
        #pragma unroll
        for (int mt = 0; mt < 2; mt++)
            #pragma unroll
            for (int nt = 0; nt < 2; nt++)
                mma_f16(acc[mt][nt], a[mt], bb[nt]);
    }
}

// relu + f16 store of the 32x16 warp tile into Out[64][LDW]
__device__ __forceinline__ void store_relu_f16(
    __half* __restrict__ Out, float (&acc)[2][2][4],
    int mb, int nb, int g, int q)
{
    #pragma unroll
    for (int mt = 0; mt < 2; mt++)
        #pragma unroll
        for (int nt = 0; nt < 2; nt++) {
            int r0 = mb + 16 * mt + g;
            int c  = nb + 8 * nt + 2 * q;
            __half2 v0 = __floats2half2_rn(fmaxf(acc[mt][nt][0], 0.f),
                                           fmaxf(acc[mt][nt][1], 0.f));
            __half2 v1 = __floats2half2_rn(fmaxf(acc[mt][nt][2], 0.f),
                                           fmaxf(acc[mt][nt][3], 0.f));
            *(__half2*)(Out + r0 * LDW + c)       = v0;
            *(__half2*)(Out + (r0 + 8) * LDW + c) = v1;
        }
}

// ---------------------------------------------------------------------------
// Main persistent kernel
// ---------------------------------------------------------------------------
struct __align__(16) Smem {
    __half W2s[D * LDW];      // w_r2_w^T   [n][k]
    __half A1ts[D * LDW];     // att1_w top^T [n][k]
    __half A2s[D * LDW];      // att2_w^T   [n][k]
    __half Hbuf[D * LDW];     // activations [l][k]
    __half Obuf[D * LDW];     // o_history f16 [l][j]
    float  Of32[D * LDO];     // o_history f32 [l][j]
    float  A1B[D * D];        // att1_w rows 64..127 (f32, for u_att)
    float  rpre[NR * D];
    float  a3s[D];
    float  b_r2[D];
    float  b_a1[D];
    float  b_a2[D];
    float  uvs[D];
    float  u_att[D];
    float  lpart[D * 4];      // per-row logit partials, one slot per n-warp
    float  logits[D];
    float  attw[D];
    float  b_a3;
    int    items[L_HIST];
    int    rats[L_HIST];
};

__global__ void __launch_bounds__(256, 2)
uv_agg_main(const int* __restrict__ nodes,
            const int* __restrict__ huv,
            const int* __restrict__ hr,
            const float* __restrict__ u2e,
            const float* __restrict__ w2w, const float* __restrict__ w2b,
            const float* __restrict__ a1w, const float* __restrict__ a1b,
            const float* __restrict__ a2w, const float* __restrict__ a2b,
            const float* __restrict__ a3w, const float* __restrict__ a3b,
            float* __restrict__ out)
{
    extern __shared__ __align__(16) char sraw[];
    Smem& s = *reinterpret_cast<Smem*>(sraw);
    const int t    = threadIdx.x;
    const int wid  = t >> 5;
    const int lane = t & 31;
    const int g    = lane >> 2;     // group id (0..7)
    const int q    = lane & 3;      // thread-in-group (0..3)
    const int mb   = (wid >> 2) * 32;   // warp row-block (0 or 32)
    const int nb   = (wid & 3) * 16;    // warp col-block (0,16,32,48)

    // One-time weight staging per block: store W^T as f16 [n][k]
    for (int i = t; i < 3 * D * D; i += 256) {
        int mat = i >> 12, w = i & 4095;
        int n = w >> 6, k = w & 63;
        const float* W = (mat == 0) ? w2w : (mat == 1) ? a1w : a2w;
        __half h = __float2half_rn(W[k * D + n]);
        if (mat == 0)      s.W2s [n * LDW + k] = h;
        else if (mat == 1) s.A1ts[n * LDW + k] = h;
        else               s.A2s [n * LDW + k] = h;
    }
    for (int i = t; i < D * D; i += 256) s.A1B[i] = a1w[D * D + i];
    if (t < D) {
        s.a3s[t]  = a3w[t];
        s.b_r2[t] = w2b[t];
        s.b_a1[t] = a1b[t];
        s.b_a2[t] = a2b[t];
    }
    for (int i = t; i < NR * D; i += 256) s.rpre[i] = g_r_pre[i];
    if (t == 0) s.b_a3 = a3b[0];
    __syncthreads();

    for (int b = blockIdx.x; b < B_NODES; b += gridDim.x) {
        // ---- gather indices + uv embedding ----
        if (t < L_HIST) {
            s.items[t] = huv[b * L_HIST + t];
            s.rats[t]  = hr[b * L_HIST + t];
        }
        if (t >= 64 && t < 128) {
            int node = nodes[b];
            s.uvs[t - 64] = u2e[node * D + (t - 64)];
        }
        __syncthreads();

        // ---- Hbuf[l][k] = f16(relu(h_pre[item_l][k] + r_pre[r_l][k])) ----
        for (int idx = t; idx < 512; idx += 256) {   // 64 rows x 8 chunks of 8
            int l = idx >> 3, c8 = (idx & 7) * 8;
            __half2 v[4];
            if (l < L_HIST) {
                const float* hp = g_h_pre + s.items[l] * D + c8;
                const float* rp = s.rpre + s.rats[l] * D + c8;
                float4 h0 = *(const float4*)hp;
                float4 h1 = *(const float4*)(hp + 4);
                float4 r0 = *(const float4*)rp;
                float4 r1 = *(const float4*)(rp + 4);
                v[0] = __floats2half2_rn(fmaxf(h0.x + r0.x, 0.f), fmaxf(h0.y + r0.y, 0.f));
                v[1] = __floats2half2_rn(fmaxf(h0.z + r0.z, 0.f), fmaxf(h0.w + r0.w, 0.f));
                v[2] = __floats2half2_rn(fmaxf(h1.x + r1.x, 0.f), fmaxf(h1.y + r1.y, 0.f));
                v[3] = __floats2half2_rn(fmaxf(h1.z + r1.z, 0.f), fmaxf(h1.w + r1.w, 0.f));
            } else {
                v[0] = v[1] = v[2] = v[3] = __floats2half2_rn(0.f, 0.f);
            }
            *(float4*)(s.Hbuf + l * LDW + c8) = *(float4*)v;
        }
        // ---- u_att[j] = uv @ A1B[:,j] + b_a1[j] (f32) ----
        if (t < D) {
            float acc = s.b_a1[t];
            #pragma unroll 16
            for (int k = 0; k < D; k++)
                acc = fmaf(s.uvs[k], s.A1B[k * D + t], acc);
            s.u_att[t] = acc;
        }
        __syncthreads();

        float acc[2][2][4];

        // GEMM A: O = relu(H @ W2 + b_r2) -> Obuf (f16) + Of32
        run_mma_gemm(s.Hbuf, s.W2s, s.b_r2, acc, mb, nb, g, q);
        store_relu_f16(s.Obuf, acc, mb, nb, g, q);
        #pragma unroll
        for (int mt = 0; mt < 2; mt++)
            #pragma unroll
            for (int nt = 0; nt < 2; nt++) {
                int r0 = mb + 16 * mt + g;
                int c  = nb + 8 * nt + 2 * q;
                *(float2*)(s.Of32 + r0 * LDO + c) =
                    make_float2(fmaxf(acc[mt][nt][0], 0.f), fmaxf(acc[mt][nt][1], 0.f));
                *(float2*)(s.Of32 + (r0 + 8) * LDO + c) =
                    make_float2(fmaxf(acc[mt][nt][2], 0.f), fmaxf(acc[mt][nt][3], 0.f));
            }
        __syncthreads();

        // GEMM B: a1 = relu(O @ A1t + u_att)  -> Hbuf
        run_mma_gemm(s.Obuf, s.A1ts, s.u_att, acc, mb, nb, g, q);
        __syncthreads();   // Hbuf consumed by GEMM A; safe to overwrite
        store_relu_f16(s.Hbuf, acc, mb, nb, g, q);
        __syncthreads();

        // GEMM C: a2 = relu(a1 @ A2 + b_a2); logits = a2 @ a3 (+ b_a3)
        run_mma_gemm(s.Hbuf, s.A2s, s.b_a2, acc, mb, nb, g, q);
        {
            float p[2][2] = {{0.f, 0.f}, {0.f, 0.f}};
            #pragma unroll
            for (int mt = 0; mt < 2; mt++)
                #pragma unroll
                for (int nt = 0; nt < 2; nt++) {
                    int c = nb + 8 * nt + 2 * q;
                    float w0 = s.a3s[c], w1 = s.a3s[c + 1];
                    p[mt][0] = fmaf(fmaxf(acc[mt][nt][0], 0.f), w0, p[mt][0]);
                    p[mt][0] = fmaf(fmaxf(acc[mt][nt][1], 0.f), w1, p[mt][0]);
                    p[mt][1] = fmaf(fmaxf(acc[mt][nt][2], 0.f), w0, p[mt][1]);
                    p[mt][1] = fmaf(fmaxf(acc[mt][nt][3], 0.f), w1, p[mt][1]);
                }
            // reduce over the 4 q-lanes (covers this warp's 16 cols)
            #pragma unroll
            for (int off = 1; off <= 2; off <<= 1) {
                #pragma unroll
                for (int mt = 0; mt < 2; mt++) {
                    p[mt][0] += __shfl_xor_sync(0xffffffffu, p[mt][0], off);
                    p[mt][1] += __shfl_xor_sync(0xffffffffu, p[mt][1], off);
                }
            }
            if (q == 0) {
                #pragma unroll
                for (int mt = 0; mt < 2; mt++) {
                    s.lpart[(mb + 16 * mt + g) * 4 + (wid & 3)]     = p[mt][0];
                    s.lpart[(mb + 16 * mt + g + 8) * 4 + (wid & 3)] = p[mt][1];
                }
            }
        }
        __syncthreads();

        if (t < D) {
            s.logits[t] = s.b_a3 + s.lpart[t * 4 + 0] + s.lpart[t * 4 + 1]
                                 + s.lpart[t * 4 + 2] + s.lpart[t * 4 + 3];
        }
        __syncthreads();

        // ---- softmax over l in [0,50), warp 0 ----
        if (t < 32) {
            float v1 = s.logits[t];
            float v2 = (t + 32 < L_HIST) ? s.logits[t + 32] : -1e30f;
            float m = fmaxf(v1, v2);
            #pragma unroll
            for (int off = 16; off >= 1; off >>= 1)
                m = fmaxf(m, __shfl_xor_sync(0xffffffffu, m, off));
            float e1 = __expf(v1 - m);
            float e2 = (t + 32 < L_HIST) ? __expf(v2 - m) : 0.f;
            float ssum = e1 + e2;
            #pragma unroll
            for (int off = 16; off >= 1; off >>= 1)
                ssum += __shfl_xor_sync(0xffffffffu, ssum, off);
            float inv = 1.f / ssum;
            s.attw[t] = e1 * inv;
            if (t + 32 < L_HIST) s.attw[t + 32] = e2 * inv;
        }
        __syncthreads();

        // ---- out[b][j] = sum_l attw[l] * o[l][j] (f32 copy) ----
        if (t < D) {
            float acc2 = 0.f;
            #pragma unroll
            for (int l = 0; l < L_HIST; l++)
                acc2 = fmaf(s.attw[l], s.Of32[l * LDO + t], acc2);
            out[b * D + t] = acc2;
        }
        __syncthreads();   // protect smem before next node iteration
    }
}

// ---------------------------------------------------------------------------
extern "C" void kernel_launch(void* const* d_in, const int* in_sizes, int n_in,
                              void* d_out, int out_size)
{
    const int*   nodes = (const int*)d_in[0];
    const int*   huv   = (const int*)d_in[1];
    const int*   hr    = (const int*)d_in[2];
    const float* v2e   = (const float*)d_in[3];
    const float* u2e   = (const float*)d_in[4];
    const float* r2e   = (const float*)d_in[5];
    const float* w1w   = (const float*)d_in[6];
    const float* w1b   = (const float*)d_in[7];
    const float* w2w   = (const float*)d_in[8];
    const float* w2b   = (const float*)d_in[9];
    const float* a1w   = (const float*)d_in[10];
    const float* a1b   = (const float*)d_in[11];
    const float* a2w   = (const float*)d_in[12];
    const float* a2b   = (const float*)d_in[13];
    const float* a3w   = (const float*)d_in[14];
    const float* a3b   = (const float*)d_in[15];
    float* out = (float*)d_out;

    (void)in_sizes; (void)n_in; (void)out_size;

    cudaFuncSetAttribute(uv_agg_main,
                         cudaFuncAttributeMaxDynamicSharedMemorySize,
                         (int)sizeof(Smem));

    pre_r_kernel<<<1, NR * D>>>(r2e, w1w, w1b);
    pre_h_kernel<<<(NI + 63) / 64, 512>>>(v2e, w1w);
    uv_agg_main<<<296, 256, sizeof(Smem)>>>(nodes, huv, hr, u2e,
                                            w2w, w2b, a1w, a1b,
                                            a2w, a2b, a3w, a3b, out);
}

// round 5
// speedup vs baseline: 2.7773x; 1.1350x over previous
#include <cuda_runtime.h>
#include <cuda_fp16.h>
#include <cstdint>

#define B_NODES 16384
#define L_HIST  50
#define D       64
#define NI      100000
#define NR      5
#define LDW     72       // halves per row (144 B) for all f16 matrices
#define LDO     68       // floats per row for Of32
#define NPI     2        // nodes per iteration (M = 128 rows)
#define MROWS   128

// Scratch (module-static device memory; allocation-free at launch time)
__device__ float g_h_pre[NI * D];     // v2e_w @ W1_top   (25.6 MB, lives in L2)
__device__ float g_r_pre[NR * D];     // r2e_w @ W1_bot + b1

// ---------------------------------------------------------------------------
// Precompute r_pre: [5,64]
// ---------------------------------------------------------------------------
__global__ void pre_r_kernel(const float* __restrict__ r2e,
                             const float* __restrict__ w1,
                             const float* __restrict__ b1)
{
    int t = threadIdx.x;
    if (t < NR * D) {
        int r = t / D, j = t % D;
        float acc = b1[j];
        #pragma unroll 16
        for (int k = 0; k < D; k++)
            acc = fmaf(r2e[r * D + k], w1[(D + k) * D + j], acc);
        g_r_pre[t] = acc;
    }
}

// ---------------------------------------------------------------------------
// Precompute h_pre[i,:] = v2e_w[i,:] @ W1_top  (block = 64 rows, 512 threads)
// ---------------------------------------------------------------------------
__global__ void __launch_bounds__(512)
pre_h_kernel(const float* __restrict__ v2e,
             const float* __restrict__ w1)
{
    __shared__ float W1s[D * D];
    __shared__ float As[64 * D];
    int t = threadIdx.x;
    int base = blockIdx.x * 64;
    int nrow = min(64, NI - base);

    for (int i = t; i < D * D; i += 512) W1s[i] = w1[i];
    for (int i = t; i < nrow * D; i += 512) As[i] = v2e[base * D + i];
    __syncthreads();

    int row = t >> 3, cg = (t & 7) * 8;
    if (row < nrow) {
        float4 a0 = make_float4(0.f, 0.f, 0.f, 0.f);
        float4 a1 = make_float4(0.f, 0.f, 0.f, 0.f);
        #pragma unroll
        for (int k = 0; k < D; k++) {
            float a = As[row * D + k];
            float4 b0 = *(const float4*)&W1s[k * D + cg];
            float4 b1 = *(const float4*)&W1s[k * D + cg + 4];
            a0.x = fmaf(a, b0.x, a0.x); a0.y = fmaf(a, b0.y, a0.y);
            a0.z = fmaf(a, b0.z, a0.z); a0.w = fmaf(a, b0.w, a0.w);
            a1.x = fmaf(a, b1.x, a1.x); a1.y = fmaf(a, b1.y, a1.y);
            a1.z = fmaf(a, b1.z, a1.z); a1.w = fmaf(a, b1.w, a1.w);
        }
        *(float4*)&g_h_pre[(base + row) * D + cg]     = a0;
        *(float4*)&g_h_pre[(base + row) * D + cg + 4] = a1;
    }
}

// ---------------------------------------------------------------------------
// fp16 mma helper: m16n8k16 row.col, f32 accumulate
// ---------------------------------------------------------------------------
__device__ __forceinline__ void mma_f16(float (&d)[4],
                                        const uint32_t (&a)[4],
                                        const uint32_t (&b)[2])
{
    asm volatile(
        "mma.sync.aligned.m16n8k16.row.col.f32.f16.f16.f32 "
        "{%0,%1,%2,%3}, {%4,%5,%6,%7}, {%8,%9}, {%0,%1,%2,%3};\n"
        : "+f"(d[0]), "+f"(d[1]), "+f"(d[2]), "+f"(d[3])
        : "r"(a[0]), "r"(a[1]), "r"(a[2]), "r"(a[3]), "r"(b[0]), "r"(b[1]));
}

// 128x64x64 GEMM: acc += A(f16,[128][LDW]) @ Wt(f16,[n][LDW])^T
// Warp tile: 32 rows x 32 cols (2 m-tiles x 4 n-tiles of m16n8k16).
// Caller initializes acc (bias).
__device__ __forceinline__ void run_mma_gemm128(
    const __half* __restrict__ Ab, const __half* __restrict__ Wt,
    float (&acc)[2][4][4], int mb, int nbk, int g, int q)
{
    #pragma unroll
    for (int ks = 0; ks < 4; ks++) {
        const int kb = ks * 16;
        uint32_t a[2][4], bb[4][2];
        #pragma unroll
        for (int mt = 0; mt < 2; mt++) {
            const __half* ap = Ab + (mb + 16 * mt + g) * LDW + kb + 2 * q;
            a[mt][0] = *(const uint32_t*)(ap);
            a[mt][1] = *(const uint32_t*)(ap + 8 * LDW);
            a[mt][2] = *(const uint32_t*)(ap + 8);
            a[mt][3] = *(const uint32_t*)(ap + 8 * LDW + 8);
        }
        #pragma unroll
        for (int nt = 0; nt < 4; nt++) {
            const __half* bp = Wt + (nbk + 8 * nt + g) * LDW + kb + 2 * q;
            bb[nt][0] = *(const uint32_t*)(bp);
            bb[nt][1] = *(const uint32_t*)(bp + 8);
        }
        #pragma unroll
        for (int mt = 0; mt < 2; mt++)
            #pragma unroll
            for (int nt = 0; nt < 4; nt++)
                mma_f16(acc[mt][nt], a[mt], bb[nt]);
    }
}

// relu + f16 store of the 32x32 warp tile into Out[128][LDW]
__device__ __forceinline__ void store_relu_f16_128(
    __half* __restrict__ Out, float (&acc)[2][4][4],
    int mb, int nbk, int g, int q)
{
    #pragma unroll
    for (int mt = 0; mt < 2; mt++)
        #pragma unroll
        for (int nt = 0; nt < 4; nt++) {
            int r0 = mb + 16 * mt + g;
            int c  = nbk + 8 * nt + 2 * q;
            __half2 v0 = __floats2half2_rn(fmaxf(acc[mt][nt][0], 0.f),
                                           fmaxf(acc[mt][nt][1], 0.f));
            __half2 v1 = __floats2half2_rn(fmaxf(acc[mt][nt][2], 0.f),
                                           fmaxf(acc[mt][nt][3], 0.f));
            *(__half2*)(Out + r0 * LDW + c)       = v0;
            *(__half2*)(Out + (r0 + 8) * LDW + c) = v1;
        }
}

// ---------------------------------------------------------------------------
// Main persistent kernel
// ---------------------------------------------------------------------------
struct __align__(16) Smem {
    __half W2s[D * LDW];        // w_r2_w^T   [n][k]
    __half A1ts[D * LDW];       // att1_w top^T [n][k]
    __half A2s[D * LDW];        // att2_w^T   [n][k]
    __half Hbuf[MROWS * LDW];   // activations [node*64+l][k]
    __half Obuf[MROWS * LDW];   // o_history f16
    float  Of32[MROWS * LDO];   // o_history f32
    __half A1Bh[D * D];         // att1_w rows 64..127 (f16, [k][j])
    float  rpre[NR * D];
    float  a3s[D];
    float  b_r2[D];
    float  b_a2[D];
    float  b_a1[D];
    float  uvs[NPI * D];
    float  u_att[NPI * D];
    float  lpart[MROWS * 2];    // per-row logit partials (2 col-warp-groups)
    float  attw[MROWS];
    int    items[MROWS];
    int    rats[MROWS];
};

__global__ void __launch_bounds__(256, 2)
uv_agg_main(const int* __restrict__ nodes,
            const int* __restrict__ huv,
            const int* __restrict__ hr,
            const float* __restrict__ u2e,
            const float* __restrict__ w2w, const float* __restrict__ w2b,
            const float* __restrict__ a1w, const float* __restrict__ a1b,
            const float* __restrict__ a2w, const float* __restrict__ a2b,
            const float* __restrict__ a3w, const float* __restrict__ a3b,
            float* __restrict__ out)
{
    extern __shared__ __align__(16) char sraw[];
    Smem& s = *reinterpret_cast<Smem*>(sraw);
    const int t    = threadIdx.x;
    const int wid  = t >> 5;
    const int lane = t & 31;
    const int g    = lane >> 2;       // group id (0..7)
    const int q    = lane & 3;        // thread-in-group (0..3)
    const int mb   = (wid & 3) * 32;  // warp row-block (0,32,64,96)
    const int nbk  = (wid >> 2) * 32; // warp col-block (0,32)
    const int cw   = wid >> 2;        // col-warp-group (0,1)

    // One-time weight staging per block: store W^T as f16 [n][k]
    for (int i = t; i < 3 * D * D; i += 256) {
        int mat = i >> 12, w = i & 4095;
        int n = w >> 6, k = w & 63;
        const float* W = (mat == 0) ? w2w : (mat == 1) ? a1w : a2w;
        __half h = __float2half_rn(W[k * D + n]);
        if (mat == 0)      s.W2s [n * LDW + k] = h;
        else if (mat == 1) s.A1ts[n * LDW + k] = h;
        else               s.A2s [n * LDW + k] = h;
    }
    for (int i = t; i < D * D; i += 256)
        s.A1Bh[i] = __float2half_rn(a1w[D * D + i]);
    if (t < D) {
        s.a3s[t]  = a3w[t];
        s.b_r2[t] = w2b[t];
        s.b_a1[t] = a1b[t];
        s.b_a2[t] = a2b[t];
    }
    for (int i = t; i < NR * D; i += 256) s.rpre[i] = g_r_pre[i];
    __syncthreads();

    for (int nb = blockIdx.x * NPI; nb < B_NODES; nb += gridDim.x * NPI) {
        // ---- gather indices + uv embeddings (2 nodes) ----
        if (t < MROWS) {
            int node = t >> 6, l = t & 63;
            if (l < L_HIST) {
                s.items[t] = huv[(nb + node) * L_HIST + l];
                s.rats[t]  = hr[(nb + node) * L_HIST + l];
            }
        } else {
            int u = t - MROWS;
            int node = u >> 6, j = u & 63;
            s.uvs[u] = u2e[nodes[nb + node] * D + j];
        }
        __syncthreads();

        // ---- Hbuf[node*64+l][k] = f16(relu(h_pre + r_pre)), valid rows only ----
        for (int idx = t; idx < 2 * L_HIST * 8; idx += 256) {  // 100 rows x 8 chunks
            int vrow = idx >> 3, c8 = (idx & 7) * 8;
            int node = (vrow >= L_HIST) ? 1 : 0;
            int l = vrow - node * L_HIST;
            int r = node * 64 + l;
            const float* hp = g_h_pre + s.items[r] * D + c8;
            const float* rp = s.rpre + s.rats[r] * D + c8;
            float4 h0 = *(const float4*)hp;
            float4 h1 = *(const float4*)(hp + 4);
            float4 r0 = *(const float4*)rp;
            float4 r1 = *(const float4*)(rp + 4);
            __half2 v[4];
            v[0] = __floats2half2_rn(fmaxf(h0.x + r0.x, 0.f), fmaxf(h0.y + r0.y, 0.f));
            v[1] = __floats2half2_rn(fmaxf(h0.z + r0.z, 0.f), fmaxf(h0.w + r0.w, 0.f));
            v[2] = __floats2half2_rn(fmaxf(h1.x + r1.x, 0.f), fmaxf(h1.y + r1.y, 0.f));
            v[3] = __floats2half2_rn(fmaxf(h1.z + r1.z, 0.f), fmaxf(h1.w + r1.w, 0.f));
            *(float4*)(s.Hbuf + r * LDW + c8) = *(float4*)v;
        }
        // ---- u_att[node][j] = uv[node] @ A1B[:,j] + b_a1[j] ----
        if (t < NPI * D) {
            int node = t >> 6, j = t & 63;
            float acc = s.b_a1[j];
            const float* uv = s.uvs + node * D;
            #pragma unroll 16
            for (int k = 0; k < D; k++)
                acc = fmaf(uv[k], __half2float(s.A1Bh[k * D + j]), acc);
            s.u_att[t] = acc;
        }
        __syncthreads();

        float acc[2][4][4];

        // ============ GEMM A: O = relu(H @ W2 + b_r2) -> Obuf f16 + Of32 ============
        #pragma unroll
        for (int mt = 0; mt < 2; mt++)
            #pragma unroll
            for (int nt = 0; nt < 4; nt++) {
                int c = nbk + 8 * nt + 2 * q;
                float b0 = s.b_r2[c], b1 = s.b_r2[c + 1];
                acc[mt][nt][0] = b0; acc[mt][nt][1] = b1;
                acc[mt][nt][2] = b0; acc[mt][nt][3] = b1;
            }
        run_mma_gemm128(s.Hbuf, s.W2s, acc, mb, nbk, g, q);
        store_relu_f16_128(s.Obuf, acc, mb, nbk, g, q);
        #pragma unroll
        for (int mt = 0; mt < 2; mt++)
            #pragma unroll
            for (int nt = 0; nt < 4; nt++) {
                int r0 = mb + 16 * mt + g;
                int c  = nbk + 8 * nt + 2 * q;
                *(float2*)(s.Of32 + r0 * LDO + c) =
                    make_float2(fmaxf(acc[mt][nt][0], 0.f), fmaxf(acc[mt][nt][1], 0.f));
                *(float2*)(s.Of32 + (r0 + 8) * LDO + c) =
                    make_float2(fmaxf(acc[mt][nt][2], 0.f), fmaxf(acc[mt][nt][3], 0.f));
            }
        __syncthreads();

        // ============ GEMM B: a1 = relu(O @ A1t + u_att[node]) -> Hbuf ============
        #pragma unroll
        for (int mt = 0; mt < 2; mt++) {
            const float* ua = s.u_att + ((mb + 16 * mt) >> 6) * D;
            #pragma unroll
            for (int nt = 0; nt < 4; nt++) {
                int c = nbk + 8 * nt + 2 * q;
                float b0 = ua[c], b1 = ua[c + 1];
                acc[mt][nt][0] = b0; acc[mt][nt][1] = b1;
                acc[mt][nt][2] = b0; acc[mt][nt][3] = b1;
            }
        }
        run_mma_gemm128(s.Obuf, s.A1ts, acc, mb, nbk, g, q);
        store_relu_f16_128(s.Hbuf, acc, mb, nbk, g, q);   // Hbuf already consumed
        __syncthreads();

        // ====== GEMM C: a2 = relu(a1 @ A2 + b_a2); logits = relu(a2) @ a3 ======
        #pragma unroll
        for (int mt = 0; mt < 2; mt++)
            #pragma unroll
            for (int nt = 0; nt < 4; nt++) {
                int c = nbk + 8 * nt + 2 * q;
                float b0 = s.b_a2[c], b1 = s.b_a2[c + 1];
                acc[mt][nt][0] = b0; acc[mt][nt][1] = b1;
                acc[mt][nt][2] = b0; acc[mt][nt][3] = b1;
            }
        run_mma_gemm128(s.Hbuf, s.A2s, acc, mb, nbk, g, q);
        {
            float p[2][2] = {{0.f, 0.f}, {0.f, 0.f}};
            #pragma unroll
            for (int mt = 0; mt < 2; mt++)
                #pragma unroll
                for (int nt = 0; nt < 4; nt++) {
                    int c = nbk + 8 * nt + 2 * q;
                    float w0 = s.a3s[c], w1 = s.a3s[c + 1];
                    p[mt][0] = fmaf(fmaxf(acc[mt][nt][0], 0.f), w0, p[mt][0]);
                    p[mt][0] = fmaf(fmaxf(acc[mt][nt][1], 0.f), w1, p[mt][0]);
                    p[mt][1] = fmaf(fmaxf(acc[mt][nt][2], 0.f), w0, p[mt][1]);
                    p[mt][1] = fmaf(fmaxf(acc[mt][nt][3], 0.f), w1, p[mt][1]);
                }
            #pragma unroll
            for (int off = 1; off <= 2; off <<= 1) {
                #pragma unroll
                for (int mt = 0; mt < 2; mt++) {
                    p[mt][0] += __shfl_xor_sync(0xffffffffu, p[mt][0], off);
                    p[mt][1] += __shfl_xor_sync(0xffffffffu, p[mt][1], off);
                }
            }
            if (q == 0) {
                #pragma unroll
                for (int mt = 0; mt < 2; mt++) {
                    s.lpart[(mb + 16 * mt + g) * 2 + cw]     = p[mt][0];
                    s.lpart[(mb + 16 * mt + g + 8) * 2 + cw] = p[mt][1];
                }
            }
        }
        __syncthreads();

        // ---- softmax: warp 0 -> node 0, warp 1 -> node 1 (b_a3 cancels) ----
        if (t < 64) {
            int node = wid;
            int r1 = node * 64 + lane;
            float v1 = s.lpart[r1 * 2] + s.lpart[r1 * 2 + 1];
            float v2 = -1e30f;
            if (lane + 32 < L_HIST) {
                int r2 = r1 + 32;
                v2 = s.lpart[r2 * 2] + s.lpart[r2 * 2 + 1];
            }
            float m = fmaxf(v1, v2);
            #pragma unroll
            for (int off = 16; off >= 1; off >>= 1)
                m = fmaxf(m, __shfl_xor_sync(0xffffffffu, m, off));
            float e1 = __expf(v1 - m);
            float e2 = (lane + 32 < L_HIST) ? __expf(v2 - m) : 0.f;
            float ssum = e1 + e2;
            #pragma unroll
            for (int off = 16; off >= 1; off >>= 1)
                ssum += __shfl_xor_sync(0xffffffffu, ssum, off);
            float inv = 1.f / ssum;
            s.attw[r1] = e1 * inv;
            if (lane + 32 < L_HIST) s.attw[r1 + 32] = e2 * inv;
        }
        __syncthreads();

        // ---- out[(nb+node)][j] = sum_l attw[node*64+l] * Of32[node*64+l][j] ----
        if (t < MROWS) {
            int node = t >> 6, j = t & 63;
            const float* aw = s.attw + node * 64;
            const float* oc = s.Of32 + node * 64 * LDO + j;
            float acc2 = 0.f;
            #pragma unroll
            for (int l = 0; l < L_HIST; l++)
                acc2 = fmaf(aw[l], oc[l * LDO], acc2);
            out[(nb + node) * D + j] = acc2;
        }
        // no trailing sync needed: next iteration's first writes (items/rats/uvs)
        // do not alias anything read after the last sync above
        __syncthreads();
    }
}

// ---------------------------------------------------------------------------
extern "C" void kernel_launch(void* const* d_in, const int* in_sizes, int n_in,
                              void* d_out, int out_size)
{
    const int*   nodes = (const int*)d_in[0];
    const int*   huv   = (const int*)d_in[1];
    const int*   hr    = (const int*)d_in[2];
    const float* v2e   = (const float*)d_in[3];
    const float* u2e   = (const float*)d_in[4];
    const float* r2e   = (const float*)d_in[5];
    const float* w1w   = (const float*)d_in[6];
    const float* w1b   = (const float*)d_in[7];
    const float* w2w   = (const float*)d_in[8];
    const float* w2b   = (const float*)d_in[9];
    const float* a1w   = (const float*)d_in[10];
    const float* a1b   = (const float*)d_in[11];
    const float* a2w   = (const float*)d_in[12];
    const float* a2b   = (const float*)d_in[13];
    const float* a3w   = (const float*)d_in[14];
    const float* a3b   = (const float*)d_in[15];
    float* out = (float*)d_out;

    (void)in_sizes; (void)n_in; (void)out_size; (void)a3b;

    cudaFuncSetAttribute(uv_agg_main,
                         cudaFuncAttributeMaxDynamicSharedMemorySize,
                         (int)sizeof(Smem));

    pre_r_kernel<<<1, NR * D>>>(r2e, w1w, w1b);
    pre_h_kernel<<<(NI + 63) / 64, 512>>>(v2e, w1w);
    uv_agg_main<<<296, 256, sizeof(Smem)>>>(nodes, huv, hr, u2e,
                                            w2w, w2b, a1w, a1b,
                                            a2w, a2b, a3w, a3b, out);
}

// round 6
// speedup vs baseline: 4.2534x; 1.5315x over previous
#include <cuda_runtime.h>
#include <cuda_fp16.h>
#include <cstdint>

#define B_NODES 16384
#define L_HIST  50
#define D       64
#define NI      100000
#define NR      5
#define LDW     72       // halves per row (144 B) for all f16 matrices
#define NPI     2        // nodes per iteration (M = 128 rows)
#define MROWS   128
#define VROWS   100      // valid rows per iteration (2 x 50)
#define GRID    296
#define STRIDE  (GRID * NPI)

// Scratch (module-static device memory; allocation-free at launch time)
__device__ float g_h_pre[NI * D];     // f16-MMA( v2e ) @ W1_top  (25.6 MB, L2)
__device__ float g_r_pre[NR * D];     // r2e_w @ W1_bot + b1

// ---------------------------------------------------------------------------
// fp16 mma helper: m16n8k16 row.col, f32 accumulate
// ---------------------------------------------------------------------------
__device__ __forceinline__ void mma_f16(float (&d)[4],
                                        const uint32_t (&a)[4],
                                        const uint32_t (&b)[2])
{
    asm volatile(
        "mma.sync.aligned.m16n8k16.row.col.f32.f16.f16.f32 "
        "{%0,%1,%2,%3}, {%4,%5,%6,%7}, {%8,%9}, {%0,%1,%2,%3};\n"
        : "+f"(d[0]), "+f"(d[1]), "+f"(d[2]), "+f"(d[3])
        : "r"(a[0]), "r"(a[1]), "r"(a[2]), "r"(a[3]), "r"(b[0]), "r"(b[1]));
}

// 128x64x64 GEMM: acc += A(f16,[128][LDW]) @ Wt(f16,[n][LDW])^T
// Warp tile: 32 rows x 32 cols. Caller initializes acc.
__device__ __forceinline__ void run_mma_gemm128(
    const __half* __restrict__ Ab, const __half* __restrict__ Wt,
    float (&acc)[2][4][4], int mb, int nbk, int g, int q)
{
    #pragma unroll
    for (int ks = 0; ks < 4; ks++) {
        const int kb = ks * 16;
        uint32_t a[2][4], bb[4][2];
        #pragma unroll
        for (int mt = 0; mt < 2; mt++) {
            const __half* ap = Ab + (mb + 16 * mt + g) * LDW + kb + 2 * q;
            a[mt][0] = *(const uint32_t*)(ap);
            a[mt][1] = *(const uint32_t*)(ap + 8 * LDW);
            a[mt][2] = *(const uint32_t*)(ap + 8);
            a[mt][3] = *(const uint32_t*)(ap + 8 * LDW + 8);
        }
        #pragma unroll
        for (int nt = 0; nt < 4; nt++) {
            const __half* bp = Wt + (nbk + 8 * nt + g) * LDW + kb + 2 * q;
            bb[nt][0] = *(const uint32_t*)(bp);
            bb[nt][1] = *(const uint32_t*)(bp + 8);
        }
        #pragma unroll
        for (int mt = 0; mt < 2; mt++)
            #pragma unroll
            for (int nt = 0; nt < 4; nt++)
                mma_f16(acc[mt][nt], a[mt], bb[nt]);
    }
}

// relu + f16 store of the 32x32 warp tile into Out[128][LDW]
__device__ __forceinline__ void store_relu_f16_128(
    __half* __restrict__ Out, float (&acc)[2][4][4],
    int mb, int nbk, int g, int q)
{
    #pragma unroll
    for (int mt = 0; mt < 2; mt++)
        #pragma unroll
        for (int nt = 0; nt < 4; nt++) {
            int r0 = mb + 16 * mt + g;
            int c  = nbk + 8 * nt + 2 * q;
            __half2 v0 = __floats2half2_rn(fmaxf(acc[mt][nt][0], 0.f),
                                           fmaxf(acc[mt][nt][1], 0.f));
            __half2 v1 = __floats2half2_rn(fmaxf(acc[mt][nt][2], 0.f),
                                           fmaxf(acc[mt][nt][3], 0.f));
            *(__half2*)(Out + r0 * LDW + c)       = v0;
            *(__half2*)(Out + (r0 + 8) * LDW + c) = v1;
        }
}

__device__ __forceinline__ void cp_async16(uint32_t dst, const void* src) {
    asm volatile("cp.async.cg.shared.global [%0], [%1], 16;"
                 :: "r"(dst), "l"(src) : "memory");
}

// ---------------------------------------------------------------------------
// Precompute: h_pre = f16MMA(v2e @ W1_top); block 0 also does r_pre (f32)
// ---------------------------------------------------------------------------
__global__ void __launch_bounds__(256)
pre_h_kernel(const float* __restrict__ v2e,
             const float* __restrict__ w1,
             const float* __restrict__ r2e,
             const float* __restrict__ b1)
{
    __shared__ __align__(16) __half W1t[D * LDW];
    __shared__ __align__(16) __half As[MROWS * LDW];
    const int t = threadIdx.x;
    const int wid = t >> 5, lane = t & 31;
    const int g = lane >> 2, q = lane & 3;
    const int mb = (wid & 3) * 32, nbk = (wid >> 2) * 32;
    const int base = blockIdx.x * MROWS;

    for (int i = t; i < D * D; i += 256) {
        int n = i >> 6, k = i & 63;
        W1t[n * LDW + k] = __float2half_rn(w1[k * D + n]);
    }
    for (int idx = t; idx < MROWS * 16; idx += 256) {
        int r = idx >> 4, c4 = (idx & 15) << 2;
        int row = base + r; if (row >= NI) row = NI - 1;
        float4 v = *(const float4*)(v2e + (size_t)row * D + c4);
        *(__half2*)(As + r * LDW + c4)     = __floats2half2_rn(v.x, v.y);
        *(__half2*)(As + r * LDW + c4 + 2) = __floats2half2_rn(v.z, v.w);
    }
    __syncthreads();

    float acc[2][4][4];
    #pragma unroll
    for (int mt = 0; mt < 2; mt++)
        #pragma unroll
        for (int nt = 0; nt < 4; nt++)
            #pragma unroll
            for (int e = 0; e < 4; e++) acc[mt][nt][e] = 0.f;
    run_mma_gemm128(As, W1t, acc, mb, nbk, g, q);

    #pragma unroll
    for (int mt = 0; mt < 2; mt++)
        #pragma unroll
        for (int nt = 0; nt < 4; nt++) {
            int r0 = base + mb + 16 * mt + g;
            int c  = nbk + 8 * nt + 2 * q;
            if (r0 < NI)
                *(float2*)(g_h_pre + (size_t)r0 * D + c) =
                    make_float2(acc[mt][nt][0], acc[mt][nt][1]);
            if (r0 + 8 < NI)
                *(float2*)(g_h_pre + (size_t)(r0 + 8) * D + c) =
                    make_float2(acc[mt][nt][2], acc[mt][nt][3]);
        }

    if (blockIdx.x == 0) {
        for (int i = t; i < NR * D; i += 256) {
            int r = i >> 6, j = i & 63;
            float a = b1[j];
            #pragma unroll 16
            for (int k = 0; k < D; k++)
                a = fmaf(r2e[r * D + k], w1[(D + k) * D + j], a);
            g_r_pre[i] = a;
        }
    }
}

// ---------------------------------------------------------------------------
// Main persistent kernel
// ---------------------------------------------------------------------------
struct __align__(16) Smem {
    __half W2s[D * LDW];        // w_r2_w^T   [n][k]
    __half A1ts[D * LDW];       // att1_w top^T [n][k]
    __half A2s[D * LDW];        // att2_w^T   [n][k]
    __half Hbuf[MROWS * LDW];   // activations [node*64+l][k]
    __half Obuf[MROWS * LDW];   // o_history f16 (GEMM B operand)
    float  stage[VROWS * D];    // cp.async staged h_pre rows (next iter)
    __half A1Bh[D * D];         // att1_w rows 64..127 (f16, [k][j])
    float  rpre[NR * D];
    float  a3s[D];
    float  b_r2[D];
    float  b_a2[D];
    float  b_a1[D];
    float  uvs[NPI * D];
    float  u_att[NPI * D];
    float  lpart[MROWS * 2];    // per-row logit partials (2 col-warp-groups)
    float  attw[MROWS];
    float  outp[4 * D];         // out partials: [mb/32][64 cols]
    int    items[VROWS];
    int    rats[VROWS];
    int    nodesbuf[NPI];
};

__global__ void __launch_bounds__(256, 2)
uv_agg_main(const int* __restrict__ nodes,
            const int* __restrict__ huv,
            const int* __restrict__ hr,
            const float* __restrict__ u2e,
            const float* __restrict__ w2w, const float* __restrict__ w2b,
            const float* __restrict__ a1w, const float* __restrict__ a1b,
            const float* __restrict__ a2w, const float* __restrict__ a2b,
            const float* __restrict__ a3w, const float* __restrict__ a3b,
            float* __restrict__ out)
{
    extern __shared__ __align__(16) char sraw[];
    Smem& s = *reinterpret_cast<Smem*>(sraw);
    const int t    = threadIdx.x;
    const int wid  = t >> 5;
    const int lane = t & 31;
    const int g    = lane >> 2;
    const int q    = lane & 3;
    const int mb   = (wid & 3) * 32;  // warp row-block (0,32,64,96)
    const int nbk  = (wid >> 2) * 32; // warp col-block (0,32)
    const int cw   = wid >> 2;
    const uint32_t stage_u32 = (uint32_t)__cvta_generic_to_shared(s.stage);

    // ---- one-time weight staging ----
    for (int i = t; i < 3 * D * D; i += 256) {
        int mat = i >> 12, w = i & 4095;
        int n = w >> 6, k = w & 63;
        const float* W = (mat == 0) ? w2w : (mat == 1) ? a1w : a2w;
        __half h = __float2half_rn(W[k * D + n]);
        if (mat == 0)      s.W2s [n * LDW + k] = h;
        else if (mat == 1) s.A1ts[n * LDW + k] = h;
        else               s.A2s [n * LDW + k] = h;
    }
    for (int i = t; i < D * D; i += 256)
        s.A1Bh[i] = __float2half_rn(a1w[D * D + i]);
    if (t < D) {
        s.a3s[t]  = a3w[t];
        s.b_r2[t] = w2b[t];
        s.b_a1[t] = a1b[t];
        s.b_a2[t] = a2b[t];
    }
    for (int i = t; i < NR * D; i += 256) s.rpre[i] = g_r_pre[i];

    // ---- prologue: iter-0 indices ----
    const int nb0 = blockIdx.x * NPI;
    if (t < VROWS) {
        int node = (t >= L_HIST);
        int l = t - L_HIST * node;
        int gi = (nb0 + node) * L_HIST + l;
        s.items[t] = huv[gi];
        s.rats[t]  = hr[gi];
    }
    if (t >= 200 && t < 200 + NPI)
        s.nodesbuf[t - 200] = nodes[nb0 + t - 200];
    __syncthreads();

    // ---- prologue: stage iter-0 h_pre + uv ----
    for (int c = t; c < VROWS * 16; c += 256) {
        int v = c >> 4, k4 = (c & 15) << 2;
        cp_async16(stage_u32 + (uint32_t)(v * D + k4) * 4,
                   g_h_pre + (size_t)s.items[v] * D + k4);
    }
    asm volatile("cp.async.commit_group;" ::: "memory");
    if (t < NPI * D)
        s.uvs[t] = u2e[(size_t)s.nodesbuf[t >> 6] * D + (t & 63)];
    asm volatile("cp.async.wait_group 0;" ::: "memory");
    __syncthreads();

    for (int nb = nb0; nb < B_NODES; nb += STRIDE) {
        const int nb2 = nb + STRIDE;
        const bool pf = nb2 < B_NODES;

        // ======== phase 0: convert staged rows -> Hbuf f16 ; u_att ========
        for (int idx = t; idx < VROWS * 8; idx += 256) {
            int vrow = idx >> 3, c8 = (idx & 7) << 3;
            int r = vrow + ((vrow >= L_HIST) ? 14 : 0);   // node*64 + l
            const float* sp = s.stage + vrow * D + c8;
            const float* rp = s.rpre + s.rats[vrow] * D + c8;
            float4 h0 = *(const float4*)sp;
            float4 h1 = *(const float4*)(sp + 4);
            float4 r0 = *(const float4*)rp;
            float4 r1 = *(const float4*)(rp + 4);
            __half2 v[4];
            v[0] = __floats2half2_rn(fmaxf(h0.x + r0.x, 0.f), fmaxf(h0.y + r0.y, 0.f));
            v[1] = __floats2half2_rn(fmaxf(h0.z + r0.z, 0.f), fmaxf(h0.w + r0.w, 0.f));
            v[2] = __floats2half2_rn(fmaxf(h1.x + r1.x, 0.f), fmaxf(h1.y + r1.y, 0.f));
            v[3] = __floats2half2_rn(fmaxf(h1.z + r1.z, 0.f), fmaxf(h1.w + r1.w, 0.f));
            *(float4*)(s.Hbuf + r * LDW + c8) = *(float4*)v;
        }
        if (t < NPI * D) {
            int node = t >> 6, j = t & 63;
            float acc = s.b_a1[j];
            const float* uv = s.uvs + node * D;
            #pragma unroll 16
            for (int k = 0; k < D; k++)
                acc = fmaf(uv[k], __half2float(s.A1Bh[k * D + j]), acc);
            s.u_att[t] = acc;
        }
        __syncthreads();

        // ======== phase 1: GEMM A -> accO (relu f32, kept in regs) ========
        float accO[2][4][4];
        #pragma unroll
        for (int mt = 0; mt < 2; mt++)
            #pragma unroll
            for (int nt = 0; nt < 4; nt++) {
                int c = nbk + 8 * nt + 2 * q;
                float b0 = s.b_r2[c], b1 = s.b_r2[c + 1];
                accO[mt][nt][0] = b0; accO[mt][nt][1] = b1;
                accO[mt][nt][2] = b0; accO[mt][nt][3] = b1;
            }
        run_mma_gemm128(s.Hbuf, s.W2s, accO, mb, nbk, g, q);
        #pragma unroll
        for (int mt = 0; mt < 2; mt++)
            #pragma unroll
            for (int nt = 0; nt < 4; nt++)
                #pragma unroll
                for (int e = 0; e < 4; e++)
                    accO[mt][nt][e] = fmaxf(accO[mt][nt][e], 0.f);
        #pragma unroll
        for (int mt = 0; mt < 2; mt++)
            #pragma unroll
            for (int nt = 0; nt < 4; nt++) {
                int r0 = mb + 16 * mt + g;
                int c  = nbk + 8 * nt + 2 * q;
                *(__half2*)(s.Obuf + r0 * LDW + c) =
                    __floats2half2_rn(accO[mt][nt][0], accO[mt][nt][1]);
                *(__half2*)(s.Obuf + (r0 + 8) * LDW + c) =
                    __floats2half2_rn(accO[mt][nt][2], accO[mt][nt][3]);
            }
        __syncthreads();

        // ======== phase 2: prefetch idx (regs) ; GEMM B -> Hbuf ========
        int it2 = 0, rt2 = 0, nd2 = 0;
        if (t < VROWS) {
            int node = (t >= L_HIST);
            int l = t - L_HIST * node;
            int gi = pf ? ((nb2 + node) * L_HIST + l) : 0;
            it2 = huv[gi];
            rt2 = hr[gi];
        }
        if (t >= 200 && t < 200 + NPI)
            nd2 = nodes[pf ? (nb2 + t - 200) : 0];

        float acc[2][4][4];
        #pragma unroll
        for (int mt = 0; mt < 2; mt++) {
            const float* ua = s.u_att + ((mb + 16 * mt) >> 6) * D;
            #pragma unroll
            for (int nt = 0; nt < 4; nt++) {
                int c = nbk + 8 * nt + 2 * q;
                float b0 = ua[c], b1 = ua[c + 1];
                acc[mt][nt][0] = b0; acc[mt][nt][1] = b1;
                acc[mt][nt][2] = b0; acc[mt][nt][3] = b1;
            }
        }
        run_mma_gemm128(s.Obuf, s.A1ts, acc, mb, nbk, g, q);
        store_relu_f16_128(s.Hbuf, acc, mb, nbk, g, q);

        if (t < VROWS) { s.items[t] = it2; s.rats[t] = rt2; }
        if (t >= 200 && t < 200 + NPI) s.nodesbuf[t - 200] = nd2;
        __syncthreads();

        // ======== phase 3: cp.async stage(next) ; uv prefetch ; GEMM C ========
        for (int c = t; c < VROWS * 16; c += 256) {
            int v = c >> 4, k4 = (c & 15) << 2;
            cp_async16(stage_u32 + (uint32_t)(v * D + k4) * 4,
                       g_h_pre + (size_t)s.items[v] * D + k4);
        }
        asm volatile("cp.async.commit_group;" ::: "memory");
        float uvreg = 0.f;
        if (t < NPI * D)
            uvreg = u2e[(size_t)s.nodesbuf[t >> 6] * D + (t & 63)];

        #pragma unroll
        for (int mt = 0; mt < 2; mt++)
            #pragma unroll
            for (int nt = 0; nt < 4; nt++) {
                int c = nbk + 8 * nt + 2 * q;
                float b0 = s.b_a2[c], b1 = s.b_a2[c + 1];
                acc[mt][nt][0] = b0; acc[mt][nt][1] = b1;
                acc[mt][nt][2] = b0; acc[mt][nt][3] = b1;
            }
        run_mma_gemm128(s.Hbuf, s.A2s, acc, mb, nbk, g, q);
        {
            float p[2][2] = {{0.f, 0.f}, {0.f, 0.f}};
            #pragma unroll
            for (int mt = 0; mt < 2; mt++)
                #pragma unroll
                for (int nt = 0; nt < 4; nt++) {
                    int c = nbk + 8 * nt + 2 * q;
                    float w0 = s.a3s[c], w1 = s.a3s[c + 1];
                    p[mt][0] = fmaf(fmaxf(acc[mt][nt][0], 0.f), w0, p[mt][0]);
                    p[mt][0] = fmaf(fmaxf(acc[mt][nt][1], 0.f), w1, p[mt][0]);
                    p[mt][1] = fmaf(fmaxf(acc[mt][nt][2], 0.f), w0, p[mt][1]);
                    p[mt][1] = fmaf(fmaxf(acc[mt][nt][3], 0.f), w1, p[mt][1]);
                }
            #pragma unroll
            for (int off = 1; off <= 2; off <<= 1) {
                #pragma unroll
                for (int mt = 0; mt < 2; mt++) {
                    p[mt][0] += __shfl_xor_sync(0xffffffffu, p[mt][0], off);
                    p[mt][1] += __shfl_xor_sync(0xffffffffu, p[mt][1], off);
                }
            }
            if (q == 0) {
                #pragma unroll
                for (int mt = 0; mt < 2; mt++) {
                    s.lpart[(mb + 16 * mt + g) * 2 + cw]     = p[mt][0];
                    s.lpart[(mb + 16 * mt + g + 8) * 2 + cw] = p[mt][1];
                }
            }
        }
        __syncthreads();

        // ======== phase 4: softmax (warps 0/1) ; stash uv ========
        if (t < 64) {
            int node = wid;
            int r1 = node * 64 + lane;
            float v1 = s.lpart[r1 * 2] + s.lpart[r1 * 2 + 1];
            float v2 = -1e30f;
            if (lane + 32 < L_HIST)
                v2 = s.lpart[(r1 + 32) * 2] + s.lpart[(r1 + 32) * 2 + 1];
            float m = fmaxf(v1, v2);
            #pragma unroll
            for (int off = 16; off >= 1; off >>= 1)
                m = fmaxf(m, __shfl_xor_sync(0xffffffffu, m, off));
            float e1 = __expf(v1 - m);
            float e2 = (lane + 32 < L_HIST) ? __expf(v2 - m) : 0.f;
            float ssum = e1 + e2;
            #pragma unroll
            for (int off = 16; off >= 1; off >>= 1)
                ssum += __shfl_xor_sync(0xffffffffu, ssum, off);
            float inv = 1.f / ssum;
            s.attw[r1] = e1 * inv;
            if (lane + 32 < L_HIST) s.attw[r1 + 32] = e2 * inv;
        }
        if (t < NPI * D) s.uvs[t] = uvreg;
        __syncthreads();

        // ======== phase 5: out partials from register-resident O ========
        {
            float oc[8] = {0.f, 0.f, 0.f, 0.f, 0.f, 0.f, 0.f, 0.f};
            #pragma unroll
            for (int mt = 0; mt < 2; mt++)
                #pragma unroll
                for (int rr = 0; rr < 2; rr++) {
                    int row = mb + 16 * mt + g + 8 * rr;
                    if ((row & 63) < L_HIST) {     // mask garbage rows (NaN-safe)
                        float w = s.attw[row];
                        #pragma unroll
                        for (int nt = 0; nt < 4; nt++) {
                            oc[2 * nt]     = fmaf(w, accO[mt][nt][2 * rr],     oc[2 * nt]);
                            oc[2 * nt + 1] = fmaf(w, accO[mt][nt][2 * rr + 1], oc[2 * nt + 1]);
                        }
                    }
                }
            #pragma unroll
            for (int off = 4; off <= 16; off <<= 1)
                #pragma unroll
                for (int i = 0; i < 8; i++)
                    oc[i] += __shfl_xor_sync(0xffffffffu, oc[i], off);
            if (g == 0) {
                int basep = (mb >> 5) * D;
                #pragma unroll
                for (int nt = 0; nt < 4; nt++) {
                    s.outp[basep + nbk + 8 * nt + 2 * q]     = oc[2 * nt];
                    s.outp[basep + nbk + 8 * nt + 2 * q + 1] = oc[2 * nt + 1];
                }
            }
        }
        __syncthreads();

        // ======== phase 6: final store ; then wait staged data ========
        if (t < MROWS) {
            int node = t >> 6, j = t & 63;
            out[(size_t)(nb + node) * D + j] =
                s.outp[(node * 2) * D + j] + s.outp[(node * 2 + 1) * D + j];
        }
        asm volatile("cp.async.wait_group 0;" ::: "memory");
        __syncthreads();
    }
}

// ---------------------------------------------------------------------------
extern "C" void kernel_launch(void* const* d_in, const int* in_sizes, int n_in,
                              void* d_out, int out_size)
{
    const int*   nodes = (const int*)d_in[0];
    const int*   huv   = (const int*)d_in[1];
    const int*   hr    = (const int*)d_in[2];
    const float* v2e   = (const float*)d_in[3];
    const float* u2e   = (const float*)d_in[4];
    const float* r2e   = (const float*)d_in[5];
    const float* w1w   = (const float*)d_in[6];
    const float* w1b   = (const float*)d_in[7];
    const float* w2w   = (const float*)d_in[8];
    const float* w2b   = (const float*)d_in[9];
    const float* a1w   = (const float*)d_in[10];
    const float* a1b   = (const float*)d_in[11];
    const float* a2w   = (const float*)d_in[12];
    const float* a2b   = (const float*)d_in[13];
    const float* a3w   = (const float*)d_in[14];
    const float* a3b   = (const float*)d_in[15];
    float* out = (float*)d_out;

    (void)in_sizes; (void)n_in; (void)out_size; (void)a3b;

    cudaFuncSetAttribute(uv_agg_main,
                         cudaFuncAttributeMaxDynamicSharedMemorySize,
                         (int)sizeof(Smem));

    pre_h_kernel<<<(NI + MROWS - 1) / MROWS, 256>>>(v2e, w1w, r2e, w1b);
    uv_agg_main<<<GRID, 256, sizeof(Smem)>>>(nodes, huv, hr, u2e,
                                             w2w, w2b, a1w, a1b,
                                             a2w, a2b, a3w, a3b, out);
}

// round 7
// speedup vs baseline: 4.3511x; 1.0230x over previous
#include <cuda_runtime.h>
#include <cuda_fp16.h>
#include <cstdint>

#define B_NODES 16384
#define L_HIST  50
#define D       64
#define NI      100000
#define NR      5
#define LDW     72       // halves per row (144 B) for all f16 matrices
#define NPI     2        // nodes per iteration (M = 128 rows)
#define MROWS   128
#define VROWS   100      // valid rows per iteration (2 x 50)
#define GRID    296
#define STRIDE  (GRID * NPI)

// Scratch (module-static device memory; allocation-free at launch time)
__device__ float g_h_pre[NI * D];     // f16-MMA( v2e ) @ W1_top  (25.6 MB, L2)
__device__ float g_r_pre[NR * D];     // r2e_w @ W1_bot + b1

// ---------------------------------------------------------------------------
// mma + ldmatrix helpers
// ---------------------------------------------------------------------------
__device__ __forceinline__ void mma_f16(float (&d)[4],
                                        uint32_t a0, uint32_t a1, uint32_t a2, uint32_t a3,
                                        uint32_t b0, uint32_t b1)
{
    asm volatile(
        "mma.sync.aligned.m16n8k16.row.col.f32.f16.f16.f32 "
        "{%0,%1,%2,%3}, {%4,%5,%6,%7}, {%8,%9}, {%0,%1,%2,%3};\n"
        : "+f"(d[0]), "+f"(d[1]), "+f"(d[2]), "+f"(d[3])
        : "r"(a0), "r"(a1), "r"(a2), "r"(a3), "r"(b0), "r"(b1));
}

__device__ __forceinline__ void ldsm_x4(uint32_t (&r)[4], uint32_t addr) {
    asm volatile("ldmatrix.sync.aligned.m8n8.x4.shared.b16 {%0,%1,%2,%3}, [%4];"
                 : "=r"(r[0]), "=r"(r[1]), "=r"(r[2]), "=r"(r[3]) : "r"(addr));
}

// 128x64x64 GEMM: acc += A(f16,[128][LDW]) @ Wt(f16,[n][LDW])^T
// Warp tile: 32 rows x 32 cols. Operands fetched via ldmatrix.x4.
// Caller initializes acc.
__device__ __forceinline__ void run_mma_gemm128(
    const __half* __restrict__ Ab, const __half* __restrict__ Wt,
    float (&acc)[2][4][4], int mb, int nbk, int lane)
{
    // A: lanes 0-15 -> rows 0-15 @ k=kb ; lanes 16-31 -> rows 0-15 @ k=kb+8
    uint32_t abase = (uint32_t)__cvta_generic_to_shared(Ab)
                   + (uint32_t)((((mb + (lane & 15)) * LDW) + ((lane >> 4) << 3)) << 1);
    // B: n = nbk + 8*(lane>>4) + (lane&7) ; k = kb + 8*((lane>>3)&1)
    uint32_t bbase = (uint32_t)__cvta_generic_to_shared(Wt)
                   + (uint32_t)((((nbk + ((lane >> 4) << 3) + (lane & 7)) * LDW)
                                 + (((lane >> 3) & 1) << 3)) << 1);
    #pragma unroll
    for (int ks = 0; ks < 4; ks++) {
        uint32_t a0[4], a1[4], b0[4], b1[4];
        ldsm_x4(a0, abase + 32 * ks);                 // m-tile 0: {a0,a1,a2,a3}
        ldsm_x4(a1, abase + 32 * ks + 32 * LDW);      // m-tile 1 (+16 rows)
        ldsm_x4(b0, bbase + 32 * ks);                 // nt0:{b0,b1}, nt1:{b0,b1}
        ldsm_x4(b1, bbase + 32 * ks + 32 * LDW);      // nt2, nt3 (+16 n-rows)
        mma_f16(acc[0][0], a0[0], a0[1], a0[2], a0[3], b0[0], b0[1]);
        mma_f16(acc[0][1], a0[0], a0[1], a0[2], a0[3], b0[2], b0[3]);
        mma_f16(acc[0][2], a0[0], a0[1], a0[2], a0[3], b1[0], b1[1]);
        mma_f16(acc[0][3], a0[0], a0[1], a0[2], a0[3], b1[2], b1[3]);
        mma_f16(acc[1][0], a1[0], a1[1], a1[2], a1[3], b0[0], b0[1]);
        mma_f16(acc[1][1], a1[0], a1[1], a1[2], a1[3], b0[2], b0[3]);
        mma_f16(acc[1][2], a1[0], a1[1], a1[2], a1[3], b1[0], b1[1]);
        mma_f16(acc[1][3], a1[0], a1[1], a1[2], a1[3], b1[2], b1[3]);
    }
}

// relu + f16 store of the 32x32 warp tile into Out[128][LDW]
__device__ __forceinline__ void store_relu_f16_128(
    __half* __restrict__ Out, float (&acc)[2][4][4],
    int mb, int nbk, int g, int q)
{
    #pragma unroll
    for (int mt = 0; mt < 2; mt++)
        #pragma unroll
        for (int nt = 0; nt < 4; nt++) {
            int r0 = mb + 16 * mt + g;
            int c  = nbk + 8 * nt + 2 * q;
            __half2 v0 = __floats2half2_rn(fmaxf(acc[mt][nt][0], 0.f),
                                           fmaxf(acc[mt][nt][1], 0.f));
            __half2 v1 = __floats2half2_rn(fmaxf(acc[mt][nt][2], 0.f),
                                           fmaxf(acc[mt][nt][3], 0.f));
            *(__half2*)(Out + r0 * LDW + c)       = v0;
            *(__half2*)(Out + (r0 + 8) * LDW + c) = v1;
        }
}

__device__ __forceinline__ void cp_async16(uint32_t dst, const void* src) {
    asm volatile("cp.async.cg.shared.global [%0], [%1], 16;"
                 :: "r"(dst), "l"(src) : "memory");
}

// ---------------------------------------------------------------------------
// Precompute: h_pre = f16MMA(v2e @ W1_top); block 0 also does r_pre (f32)
// ---------------------------------------------------------------------------
__global__ void __launch_bounds__(256)
pre_h_kernel(const float* __restrict__ v2e,
             const float* __restrict__ w1,
             const float* __restrict__ r2e,
             const float* __restrict__ b1)
{
    __shared__ __align__(16) __half W1t[D * LDW];
    __shared__ __align__(16) __half As[MROWS * LDW];
    const int t = threadIdx.x;
    const int wid = t >> 5, lane = t & 31;
    const int g = lane >> 2, q = lane & 3;
    const int mb = (wid & 3) * 32, nbk = (wid >> 2) * 32;
    const int base = blockIdx.x * MROWS;

    for (int i = t; i < D * D; i += 256) {
        int n = i >> 6, k = i & 63;
        W1t[n * LDW + k] = __float2half_rn(w1[k * D + n]);
    }
    for (int idx = t; idx < MROWS * 16; idx += 256) {
        int r = idx >> 4, c4 = (idx & 15) << 2;
        int row = base + r; if (row >= NI) row = NI - 1;
        float4 v = *(const float4*)(v2e + (size_t)row * D + c4);
        *(__half2*)(As + r * LDW + c4)     = __floats2half2_rn(v.x, v.y);
        *(__half2*)(As + r * LDW + c4 + 2) = __floats2half2_rn(v.z, v.w);
    }
    __syncthreads();

    float acc[2][4][4];
    #pragma unroll
    for (int mt = 0; mt < 2; mt++)
        #pragma unroll
        for (int nt = 0; nt < 4; nt++)
            #pragma unroll
            for (int e = 0; e < 4; e++) acc[mt][nt][e] = 0.f;
    run_mma_gemm128(As, W1t, acc, mb, nbk, lane);

    #pragma unroll
    for (int mt = 0; mt < 2; mt++)
        #pragma unroll
        for (int nt = 0; nt < 4; nt++) {
            int r0 = base + mb + 16 * mt + g;
            int c  = nbk + 8 * nt + 2 * q;
            if (r0 < NI)
                *(float2*)(g_h_pre + (size_t)r0 * D + c) =
                    make_float2(acc[mt][nt][0], acc[mt][nt][1]);
            if (r0 + 8 < NI)
                *(float2*)(g_h_pre + (size_t)(r0 + 8) * D + c) =
                    make_float2(acc[mt][nt][2], acc[mt][nt][3]);
        }

    if (blockIdx.x == 0) {
        for (int i = t; i < NR * D; i += 256) {
            int r = i >> 6, j = i & 63;
            float a = b1[j];
            #pragma unroll 16
            for (int k = 0; k < D; k++)
                a = fmaf(r2e[r * D + k], w1[(D + k) * D + j], a);
            g_r_pre[i] = a;
        }
    }
}

// ---------------------------------------------------------------------------
// Main persistent kernel
// ---------------------------------------------------------------------------
struct __align__(16) Smem {
    __half W2s[D * LDW];        // w_r2_w^T   [n][k]
    __half A1ts[D * LDW];       // att1_w top^T [n][k]
    __half A2s[D * LDW];        // att2_w^T   [n][k]
    __half Hbuf[MROWS * LDW];   // activations [node*64+l][k]
    __half Obuf[MROWS * LDW];   // o_history f16 (GEMM B operand)
    float  stage[VROWS * D];    // cp.async staged h_pre rows (next iter)
    __half A1Bh[D * D];         // att1_w rows 64..127 (f16, [k][j])
    float  rpre[NR * D];
    float  a3s[D];
    float  b_r2[D];
    float  b_a2[D];
    float  b_a1[D];
    float  uvs[NPI * D];
    float  u_att[NPI * D];
    float  lpart[MROWS * 2];    // per-row logit partials (2 col-warp-groups)
    float  attw[MROWS];
    float  outp[4 * D];         // out partials: [mb/32][64 cols]
    int    items[VROWS];
    int    rats[VROWS];
    int    nodesbuf[NPI];
};

__global__ void __launch_bounds__(256, 2)
uv_agg_main(const int* __restrict__ nodes,
            const int* __restrict__ huv,
            const int* __restrict__ hr,
            const float* __restrict__ u2e,
            const float* __restrict__ w2w, const float* __restrict__ w2b,
            const float* __restrict__ a1w, const float* __restrict__ a1b,
            const float* __restrict__ a2w, const float* __restrict__ a2b,
            const float* __restrict__ a3w, const float* __restrict__ a3b,
            float* __restrict__ out)
{
    extern __shared__ __align__(16) char sraw[];
    Smem& s = *reinterpret_cast<Smem*>(sraw);
    const int t    = threadIdx.x;
    const int wid  = t >> 5;
    const int lane = t & 31;
    const int g    = lane >> 2;
    const int q    = lane & 3;
    const int mb   = (wid & 3) * 32;  // warp row-block (0,32,64,96)
    const int nbk  = (wid >> 2) * 32; // warp col-block (0,32)
    const int cw   = wid >> 2;
    const uint32_t stage_u32 = (uint32_t)__cvta_generic_to_shared(s.stage);

    // ---- one-time weight staging ----
    for (int i = t; i < 3 * D * D; i += 256) {
        int mat = i >> 12, w = i & 4095;
        int n = w >> 6, k = w & 63;
        const float* W = (mat == 0) ? w2w : (mat == 1) ? a1w : a2w;
        __half h = __float2half_rn(W[k * D + n]);
        if (mat == 0)      s.W2s [n * LDW + k] = h;
        else if (mat == 1) s.A1ts[n * LDW + k] = h;
        else               s.A2s [n * LDW + k] = h;
    }
    for (int i = t; i < D * D; i += 256)
        s.A1Bh[i] = __float2half_rn(a1w[D * D + i]);
    if (t < D) {
        s.a3s[t]  = a3w[t];
        s.b_r2[t] = w2b[t];
        s.b_a1[t] = a1b[t];
        s.b_a2[t] = a2b[t];
    }
    for (int i = t; i < NR * D; i += 256) s.rpre[i] = g_r_pre[i];

    // ---- prologue: iter-0 indices ----
    const int nb0 = blockIdx.x * NPI;
    if (t < VROWS) {
        int node = (t >= L_HIST);
        int l = t - L_HIST * node;
        int gi = (nb0 + node) * L_HIST + l;
        s.items[t] = huv[gi];
        s.rats[t]  = hr[gi];
    }
    if (t >= 200 && t < 200 + NPI)
        s.nodesbuf[t - 200] = nodes[nb0 + t - 200];
    __syncthreads();

    // ---- prologue: stage iter-0 h_pre + uv ----
    for (int c = t; c < VROWS * 16; c += 256) {
        int v = c >> 4, k4 = (c & 15) << 2;
        cp_async16(stage_u32 + (uint32_t)(v * D + k4) * 4,
                   g_h_pre + (size_t)s.items[v] * D + k4);
    }
    asm volatile("cp.async.commit_group;" ::: "memory");
    if (t < NPI * D)
        s.uvs[t] = u2e[(size_t)s.nodesbuf[t >> 6] * D + (t & 63)];
    asm volatile("cp.async.wait_group 0;" ::: "memory");
    __syncthreads();

    for (int nb = nb0; nb < B_NODES; nb += STRIDE) {
        const int nb2 = nb + STRIDE;
        const bool pf = nb2 < B_NODES;

        // ======== phase 0: convert staged rows -> Hbuf f16 ; u_att ========
        for (int idx = t; idx < VROWS * 8; idx += 256) {
            int vrow = idx >> 3, c8 = (idx & 7) << 3;
            int r = vrow + ((vrow >= L_HIST) ? 14 : 0);   // node*64 + l
            const float* sp = s.stage + vrow * D + c8;
            const float* rp = s.rpre + s.rats[vrow] * D + c8;
            float4 h0 = *(const float4*)sp;
            float4 h1 = *(const float4*)(sp + 4);
            float4 r0 = *(const float4*)rp;
            float4 r1 = *(const float4*)(rp + 4);
            __half2 v[4];
            v[0] = __floats2half2_rn(fmaxf(h0.x + r0.x, 0.f), fmaxf(h0.y + r0.y, 0.f));
            v[1] = __floats2half2_rn(fmaxf(h0.z + r0.z, 0.f), fmaxf(h0.w + r0.w, 0.f));
            v[2] = __floats2half2_rn(fmaxf(h1.x + r1.x, 0.f), fmaxf(h1.y + r1.y, 0.f));
            v[3] = __floats2half2_rn(fmaxf(h1.z + r1.z, 0.f), fmaxf(h1.w + r1.w, 0.f));
            *(float4*)(s.Hbuf + r * LDW + c8) = *(float4*)v;
        }
        if (t < NPI * D) {
            int node = t >> 6, j = t & 63;
            float acc = s.b_a1[j];
            const float* uv = s.uvs + node * D;
            #pragma unroll 16
            for (int k = 0; k < D; k++)
                acc = fmaf(uv[k], __half2float(s.A1Bh[k * D + j]), acc);
            s.u_att[t] = acc;
        }
        __syncthreads();

        // ======== phase 1: GEMM A -> accO (relu f32, kept in regs) ========
        float accO[2][4][4];
        #pragma unroll
        for (int mt = 0; mt < 2; mt++)
            #pragma unroll
            for (int nt = 0; nt < 4; nt++) {
                int c = nbk + 8 * nt + 2 * q;
                float b0 = s.b_r2[c], b1 = s.b_r2[c + 1];
                accO[mt][nt][0] = b0; accO[mt][nt][1] = b1;
                accO[mt][nt][2] = b0; accO[mt][nt][3] = b1;
            }
        run_mma_gemm128(s.Hbuf, s.W2s, accO, mb, nbk, lane);
        #pragma unroll
        for (int mt = 0; mt < 2; mt++)
            #pragma unroll
            for (int nt = 0; nt < 4; nt++)
                #pragma unroll
                for (int e = 0; e < 4; e++)
                    accO[mt][nt][e] = fmaxf(accO[mt][nt][e], 0.f);
        #pragma unroll
        for (int mt = 0; mt < 2; mt++)
            #pragma unroll
            for (int nt = 0; nt < 4; nt++) {
                int r0 = mb + 16 * mt + g;
                int c  = nbk + 8 * nt + 2 * q;
                *(__half2*)(s.Obuf + r0 * LDW + c) =
                    __floats2half2_rn(accO[mt][nt][0], accO[mt][nt][1]);
                *(__half2*)(s.Obuf + (r0 + 8) * LDW + c) =
                    __floats2half2_rn(accO[mt][nt][2], accO[mt][nt][3]);
            }
        __syncthreads();

        // ======== phase 2: prefetch idx (regs) ; GEMM B -> Hbuf ========
        int it2 = 0, rt2 = 0, nd2 = 0;
        if (t < VROWS) {
            int node = (t >= L_HIST);
            int l = t - L_HIST * node;
            int gi = pf ? ((nb2 + node) * L_HIST + l) : 0;
            it2 = huv[gi];
            rt2 = hr[gi];
        }
        if (t >= 200 && t < 200 + NPI)
            nd2 = nodes[pf ? (nb2 + t - 200) : 0];

        float acc[2][4][4];
        #pragma unroll
        for (int mt = 0; mt < 2; mt++) {
            const float* ua = s.u_att + ((mb + 16 * mt) >> 6) * D;
            #pragma unroll
            for (int nt = 0; nt < 4; nt++) {
                int c = nbk + 8 * nt + 2 * q;
                float b0 = ua[c], b1 = ua[c + 1];
                acc[mt][nt][0] = b0; acc[mt][nt][1] = b1;
                acc[mt][nt][2] = b0; acc[mt][nt][3] = b1;
            }
        }
        run_mma_gemm128(s.Obuf, s.A1ts, acc, mb, nbk, lane);
        store_relu_f16_128(s.Hbuf, acc, mb, nbk, g, q);

        if (t < VROWS) { s.items[t] = it2; s.rats[t] = rt2; }
        if (t >= 200 && t < 200 + NPI) s.nodesbuf[t - 200] = nd2;
        __syncthreads();

        // ======== phase 3: cp.async stage(next) ; uv prefetch ; GEMM C ========
        for (int c = t; c < VROWS * 16; c += 256) {
            int v = c >> 4, k4 = (c & 15) << 2;
            cp_async16(stage_u32 + (uint32_t)(v * D + k4) * 4,
                       g_h_pre + (size_t)s.items[v] * D + k4);
        }
        asm volatile("cp.async.commit_group;" ::: "memory");
        float uvreg = 0.f;
        if (t < NPI * D)
            uvreg = u2e[(size_t)s.nodesbuf[t >> 6] * D + (t & 63)];

        #pragma unroll
        for (int mt = 0; mt < 2; mt++)
            #pragma unroll
            for (int nt = 0; nt < 4; nt++) {
                int c = nbk + 8 * nt + 2 * q;
                float b0 = s.b_a2[c], b1 = s.b_a2[c + 1];
                acc[mt][nt][0] = b0; acc[mt][nt][1] = b1;
                acc[mt][nt][2] = b0; acc[mt][nt][3] = b1;
            }
        run_mma_gemm128(s.Hbuf, s.A2s, acc, mb, nbk, lane);
        {
            float p[2][2] = {{0.f, 0.f}, {0.f, 0.f}};
            #pragma unroll
            for (int mt = 0; mt < 2; mt++)
                #pragma unroll
                for (int nt = 0; nt < 4; nt++) {
                    int c = nbk + 8 * nt + 2 * q;
                    float w0 = s.a3s[c], w1 = s.a3s[c + 1];
                    p[mt][0] = fmaf(fmaxf(acc[mt][nt][0], 0.f), w0, p[mt][0]);
                    p[mt][0] = fmaf(fmaxf(acc[mt][nt][1], 0.f), w1, p[mt][0]);
                    p[mt][1] = fmaf(fmaxf(acc[mt][nt][2], 0.f), w0, p[mt][1]);
                    p[mt][1] = fmaf(fmaxf(acc[mt][nt][3], 0.f), w1, p[mt][1]);
                }
            #pragma unroll
            for (int off = 1; off <= 2; off <<= 1) {
                #pragma unroll
                for (int mt = 0; mt < 2; mt++) {
                    p[mt][0] += __shfl_xor_sync(0xffffffffu, p[mt][0], off);
                    p[mt][1] += __shfl_xor_sync(0xffffffffu, p[mt][1], off);
                }
            }
            if (q == 0) {
                #pragma unroll
                for (int mt = 0; mt < 2; mt++) {
                    s.lpart[(mb + 16 * mt + g) * 2 + cw]     = p[mt][0];
                    s.lpart[(mb + 16 * mt + g + 8) * 2 + cw] = p[mt][1];
                }
            }
        }
        __syncthreads();

        // ======== phase 4: softmax (warps 0/1) ; stash uv ========
        if (t < 64) {
            int node = wid;
            int r1 = node * 64 + lane;
            float v1 = s.lpart[r1 * 2] + s.lpart[r1 * 2 + 1];
            float v2 = -1e30f;
            if (lane + 32 < L_HIST)
                v2 = s.lpart[(r1 + 32) * 2] + s.lpart[(r1 + 32) * 2 + 1];
            float m = fmaxf(v1, v2);
            #pragma unroll
            for (int off = 16; off >= 1; off >>= 1)
                m = fmaxf(m, __shfl_xor_sync(0xffffffffu, m, off));
            float e1 = __expf(v1 - m);
            float e2 = (lane + 32 < L_HIST) ? __expf(v2 - m) : 0.f;
            float ssum = e1 + e2;
            #pragma unroll
            for (int off = 16; off >= 1; off >>= 1)
                ssum += __shfl_xor_sync(0xffffffffu, ssum, off);
            float inv = 1.f / ssum;
            s.attw[r1] = e1 * inv;
            if (lane + 32 < L_HIST) s.attw[r1 + 32] = e2 * inv;
        }
        if (t < NPI * D) s.uvs[t] = uvreg;
        __syncthreads();

        // ======== phase 5: out partials from register-resident O ========
        {
            float oc[8] = {0.f, 0.f, 0.f, 0.f, 0.f, 0.f, 0.f, 0.f};
            #pragma unroll
            for (int mt = 0; mt < 2; mt++)
                #pragma unroll
                for (int rr = 0; rr < 2; rr++) {
                    int row = mb + 16 * mt + g + 8 * rr;
                    if ((row & 63) < L_HIST) {     // mask garbage rows (NaN-safe)
                        float w = s.attw[row];
                        #pragma unroll
                        for (int nt = 0; nt < 4; nt++) {
                            oc[2 * nt]     = fmaf(w, accO[mt][nt][2 * rr],     oc[2 * nt]);
                            oc[2 * nt + 1] = fmaf(w, accO[mt][nt][2 * rr + 1], oc[2 * nt + 1]);
                        }
                    }
                }
            #pragma unroll
            for (int off = 4; off <= 16; off <<= 1)
                #pragma unroll
                for (int i = 0; i < 8; i++)
                    oc[i] += __shfl_xor_sync(0xffffffffu, oc[i], off);
            if (g == 0) {
                int basep = (mb >> 5) * D;
                #pragma unroll
                for (int nt = 0; nt < 4; nt++) {
                    s.outp[basep + nbk + 8 * nt + 2 * q]     = oc[2 * nt];
                    s.outp[basep + nbk + 8 * nt + 2 * q + 1] = oc[2 * nt + 1];
                }
            }
        }
        __syncthreads();

        // ======== phase 6: final store ; then wait staged data ========
        if (t < MROWS) {
            int node = t >> 6, j = t & 63;
            out[(size_t)(nb + node) * D + j] =
                s.outp[(node * 2) * D + j] + s.outp[(node * 2 + 1) * D + j];
        }
        asm volatile("cp.async.wait_group 0;" ::: "memory");
        __syncthreads();
    }
}

// ---------------------------------------------------------------------------
extern "C" void kernel_launch(void* const* d_in, const int* in_sizes, int n_in,
                              void* d_out, int out_size)
{
    const int*   nodes = (const int*)d_in[0];
    const int*   huv   = (const int*)d_in[1];
    const int*   hr    = (const int*)d_in[2];
    const float* v2e   = (const float*)d_in[3];
    const float* u2e   = (const float*)d_in[4];
    const float* r2e   = (const float*)d_in[5];
    const float* w1w   = (const float*)d_in[6];
    const float* w1b   = (const float*)d_in[7];
    const float* w2w   = (const float*)d_in[8];
    const float* w2b   = (const float*)d_in[9];
    const float* a1w   = (const float*)d_in[10];
    const float* a1b   = (const float*)d_in[11];
    const float* a2w   = (const float*)d_in[12];
    const float* a2b   = (const float*)d_in[13];
    const float* a3w   = (const float*)d_in[14];
    const float* a3b   = (const float*)d_in[15];
    float* out = (float*)d_out;

    (void)in_sizes; (void)n_in; (void)out_size; (void)a3b;

    cudaFuncSetAttribute(uv_agg_main,
                         cudaFuncAttributeMaxDynamicSharedMemorySize,
                         (int)sizeof(Smem));

    pre_h_kernel<<<(NI + MROWS - 1) / MROWS, 256>>>(v2e, w1w, r2e, w1b);
    uv_agg_main<<<GRID, 256, sizeof(Smem)>>>(nodes, huv, hr, u2e,
                                             w2w, w2b, a1w, a1b,
                                             a2w, a2b, a3w, a3b, out);
}

// round 8
// speedup vs baseline: 5.0972x; 1.1715x over previous
#include <cuda_runtime.h>
#include <cuda_fp16.h>
#include <cstdint>

#define B_NODES 16384
#define L_HIST  50
#define D       64
#define NI      100000
#define NR      5
#define LDW     72       // halves per row (144 B) for all f16 matrices
#define NPI     2        // nodes per iteration (M = 128 rows)
#define MROWS   128
#define VROWS   100      // valid rows per iteration (2 x 50)
#define GRID    296
#define STRIDE  (GRID * NPI)

// Scratch (module-static device memory; allocation-free at launch time)
__device__ __half g_h_pre[NI * D];    // f16( f16MMA(v2e) @ W1_top )  (12.8 MB, L2)
__device__ __half g_r_pre[NR * D];    // f16( r2e_w @ W1_bot + b1 )

// ---------------------------------------------------------------------------
// mma + ldmatrix helpers
// ---------------------------------------------------------------------------
__device__ __forceinline__ void mma_f16(float (&d)[4],
                                        uint32_t a0, uint32_t a1, uint32_t a2, uint32_t a3,
                                        uint32_t b0, uint32_t b1)
{
    asm volatile(
        "mma.sync.aligned.m16n8k16.row.col.f32.f16.f16.f32 "
        "{%0,%1,%2,%3}, {%4,%5,%6,%7}, {%8,%9}, {%0,%1,%2,%3};\n"
        : "+f"(d[0]), "+f"(d[1]), "+f"(d[2]), "+f"(d[3])
        : "r"(a0), "r"(a1), "r"(a2), "r"(a3), "r"(b0), "r"(b1));
}

__device__ __forceinline__ void ldsm_x4(uint32_t (&r)[4], uint32_t addr) {
    asm volatile("ldmatrix.sync.aligned.m8n8.x4.shared.b16 {%0,%1,%2,%3}, [%4];"
                 : "=r"(r[0]), "=r"(r[1]), "=r"(r[2]), "=r"(r[3]) : "r"(addr));
}

// Load a warp's B fragments (n-slice nbk..nbk+31, all k) into registers.
__device__ __forceinline__ void load_bfrag(
    const __half* __restrict__ Wt, uint32_t (&bc)[4][8], int nbk, int lane)
{
    uint32_t bbase = (uint32_t)__cvta_generic_to_shared(Wt)
                   + (uint32_t)((((nbk + ((lane >> 4) << 3) + (lane & 7)) * LDW)
                                 + (((lane >> 3) & 1) << 3)) << 1);
    #pragma unroll
    for (int ks = 0; ks < 4; ks++) {
        uint32_t b0[4], b1[4];
        ldsm_x4(b0, bbase + 32 * ks);
        ldsm_x4(b1, bbase + 32 * ks + 32 * LDW);
        bc[ks][0] = b0[0]; bc[ks][1] = b0[1]; bc[ks][2] = b0[2]; bc[ks][3] = b0[3];
        bc[ks][4] = b1[0]; bc[ks][5] = b1[1]; bc[ks][6] = b1[2]; bc[ks][7] = b1[3];
    }
}

// 128x64x64 GEMM with register-cached B fragments.
__device__ __forceinline__ void run_mma_gemm128_cb(
    const __half* __restrict__ Ab, const uint32_t (&bc)[4][8],
    float (&acc)[2][4][4], int mb, int lane)
{
    uint32_t abase = (uint32_t)__cvta_generic_to_shared(Ab)
                   + (uint32_t)((((mb + (lane & 15)) * LDW) + ((lane >> 4) << 3)) << 1);
    #pragma unroll
    for (int ks = 0; ks < 4; ks++) {
        uint32_t a0[4], a1[4];
        ldsm_x4(a0, abase + 32 * ks);
        ldsm_x4(a1, abase + 32 * ks + 32 * LDW);
        mma_f16(acc[0][0], a0[0], a0[1], a0[2], a0[3], bc[ks][0], bc[ks][1]);
        mma_f16(acc[0][1], a0[0], a0[1], a0[2], a0[3], bc[ks][2], bc[ks][3]);
        mma_f16(acc[0][2], a0[0], a0[1], a0[2], a0[3], bc[ks][4], bc[ks][5]);
        mma_f16(acc[0][3], a0[0], a0[1], a0[2], a0[3], bc[ks][6], bc[ks][7]);
        mma_f16(acc[1][0], a1[0], a1[1], a1[2], a1[3], bc[ks][0], bc[ks][1]);
        mma_f16(acc[1][1], a1[0], a1[1], a1[2], a1[3], bc[ks][2], bc[ks][3]);
        mma_f16(acc[1][2], a1[0], a1[1], a1[2], a1[3], bc[ks][4], bc[ks][5]);
        mma_f16(acc[1][3], a1[0], a1[1], a1[2], a1[3], bc[ks][6], bc[ks][7]);
    }
}

// 128x64x64 GEMM with B from shared memory (used once per iter, GEMM C).
__device__ __forceinline__ void run_mma_gemm128(
    const __half* __restrict__ Ab, const __half* __restrict__ Wt,
    float (&acc)[2][4][4], int mb, int nbk, int lane)
{
    uint32_t abase = (uint32_t)__cvta_generic_to_shared(Ab)
                   + (uint32_t)((((mb + (lane & 15)) * LDW) + ((lane >> 4) << 3)) << 1);
    uint32_t bbase = (uint32_t)__cvta_generic_to_shared(Wt)
                   + (uint32_t)((((nbk + ((lane >> 4) << 3) + (lane & 7)) * LDW)
                                 + (((lane >> 3) & 1) << 3)) << 1);
    #pragma unroll
    for (int ks = 0; ks < 4; ks++) {
        uint32_t a0[4], a1[4], b0[4], b1[4];
        ldsm_x4(a0, abase + 32 * ks);
        ldsm_x4(a1, abase + 32 * ks + 32 * LDW);
        ldsm_x4(b0, bbase + 32 * ks);
        ldsm_x4(b1, bbase + 32 * ks + 32 * LDW);
        mma_f16(acc[0][0], a0[0], a0[1], a0[2], a0[3], b0[0], b0[1]);
        mma_f16(acc[0][1], a0[0], a0[1], a0[2], a0[3], b0[2], b0[3]);
        mma_f16(acc[0][2], a0[0], a0[1], a0[2], a0[3], b1[0], b1[1]);
        mma_f16(acc[0][3], a0[0], a0[1], a0[2], a0[3], b1[2], b1[3]);
        mma_f16(acc[1][0], a1[0], a1[1], a1[2], a1[3], b0[0], b0[1]);
        mma_f16(acc[1][1], a1[0], a1[1], a1[2], a1[3], b0[2], b0[3]);
        mma_f16(acc[1][2], a1[0], a1[1], a1[2], a1[3], b1[0], b1[1]);
        mma_f16(acc[1][3], a1[0], a1[1], a1[2], a1[3], b1[2], b1[3]);
    }
}

// relu + f16 store of the 32x32 warp tile into Out[128][LDW]
__device__ __forceinline__ void store_relu_f16_128(
    __half* __restrict__ Out, float (&acc)[2][4][4],
    int mb, int nbk, int g, int q)
{
    #pragma unroll
    for (int mt = 0; mt < 2; mt++)
        #pragma unroll
        for (int nt = 0; nt < 4; nt++) {
            int r0 = mb + 16 * mt + g;
            int c  = nbk + 8 * nt + 2 * q;
            __half2 v0 = __floats2half2_rn(fmaxf(acc[mt][nt][0], 0.f),
                                           fmaxf(acc[mt][nt][1], 0.f));
            __half2 v1 = __floats2half2_rn(fmaxf(acc[mt][nt][2], 0.f),
                                           fmaxf(acc[mt][nt][3], 0.f));
            *(__half2*)(Out + r0 * LDW + c)       = v0;
            *(__half2*)(Out + (r0 + 8) * LDW + c) = v1;
        }
}

__device__ __forceinline__ void cp_async16(uint32_t dst, const void* src) {
    asm volatile("cp.async.cg.shared.global [%0], [%1], 16;"
                 :: "r"(dst), "l"(src) : "memory");
}

// ---------------------------------------------------------------------------
// Precompute: h_pre = f16MMA(v2e @ W1_top) (stored f16); block 0: r_pre (f16)
// ---------------------------------------------------------------------------
__global__ void __launch_bounds__(256)
pre_h_kernel(const float* __restrict__ v2e,
             const float* __restrict__ w1,
             const float* __restrict__ r2e,
             const float* __restrict__ b1)
{
    __shared__ __align__(16) __half W1t[D * LDW];
    __shared__ __align__(16) __half As[MROWS * LDW];
    const int t = threadIdx.x;
    const int wid = t >> 5, lane = t & 31;
    const int g = lane >> 2, q = lane & 3;
    const int mb = (wid & 3) * 32, nbk = (wid >> 2) * 32;
    const int base = blockIdx.x * MROWS;

    for (int i = t; i < D * D; i += 256) {
        int n = i >> 6, k = i & 63;
        W1t[n * LDW + k] = __float2half_rn(w1[k * D + n]);
    }
    for (int idx = t; idx < MROWS * 16; idx += 256) {
        int r = idx >> 4, c4 = (idx & 15) << 2;
        int row = base + r; if (row >= NI) row = NI - 1;
        float4 v = *(const float4*)(v2e + (size_t)row * D + c4);
        *(__half2*)(As + r * LDW + c4)     = __floats2half2_rn(v.x, v.y);
        *(__half2*)(As + r * LDW + c4 + 2) = __floats2half2_rn(v.z, v.w);
    }
    __syncthreads();

    float acc[2][4][4];
    #pragma unroll
    for (int mt = 0; mt < 2; mt++)
        #pragma unroll
        for (int nt = 0; nt < 4; nt++)
            #pragma unroll
            for (int e = 0; e < 4; e++) acc[mt][nt][e] = 0.f;
    run_mma_gemm128(As, W1t, acc, mb, nbk, lane);

    #pragma unroll
    for (int mt = 0; mt < 2; mt++)
        #pragma unroll
        for (int nt = 0; nt < 4; nt++) {
            int r0 = base + mb + 16 * mt + g;
            int c  = nbk + 8 * nt + 2 * q;
            if (r0 < NI)
                *(__half2*)(g_h_pre + (size_t)r0 * D + c) =
                    __floats2half2_rn(acc[mt][nt][0], acc[mt][nt][1]);
            if (r0 + 8 < NI)
                *(__half2*)(g_h_pre + (size_t)(r0 + 8) * D + c) =
                    __floats2half2_rn(acc[mt][nt][2], acc[mt][nt][3]);
        }

    if (blockIdx.x == 0) {
        for (int i = t; i < NR * D; i += 256) {
            int r = i >> 6, j = i & 63;
            float a = b1[j];
            #pragma unroll 16
            for (int k = 0; k < D; k++)
                a = fmaf(r2e[r * D + k], w1[(D + k) * D + j], a);
            g_r_pre[i] = __float2half_rn(a);
        }
    }
}

// ---------------------------------------------------------------------------
// Main persistent kernel
// ---------------------------------------------------------------------------
struct __align__(16) Smem {
    __half W2s[D * LDW];        // w_r2_w^T   [n][k]
    __half A1ts[D * LDW];       // att1_w top^T [n][k]
    __half A2s[D * LDW];        // att2_w^T   [n][k]
    __half Hbuf[MROWS * LDW];   // activations [node*64+l][k]
    __half Obuf[MROWS * LDW];   // o_history f16
    __half stage[VROWS * D];    // cp.async staged h_pre rows (f16, next iter)
    __half A1Bh[D * D];         // att1_w rows 64..127 (f16, [k][j])
    __half rpre[NR * D];        // f16
    float  a3s[D];
    float  b_r2[D];
    float  b_a2[D];
    float  b_a1[D];
    float  uvs[NPI * D];
    float  u_att[NPI * D];
    float  lpart[MROWS * 2];    // per-row logit partials (2 col-warp-groups)
    float  attw[MROWS];
    float  outp[4 * D];         // out partials: [mb/32][64 cols]
    int    items[VROWS];
    int    rats[VROWS];
    int    nodesbuf[NPI];
};

__global__ void __launch_bounds__(256, 2)
uv_agg_main(const int* __restrict__ nodes,
            const int* __restrict__ huv,
            const int* __restrict__ hr,
            const float* __restrict__ u2e,
            const float* __restrict__ w2w, const float* __restrict__ w2b,
            const float* __restrict__ a1w, const float* __restrict__ a1b,
            const float* __restrict__ a2w, const float* __restrict__ a2b,
            const float* __restrict__ a3w, const float* __restrict__ a3b,
            float* __restrict__ out)
{
    extern __shared__ __align__(16) char sraw[];
    Smem& s = *reinterpret_cast<Smem*>(sraw);
    const int t    = threadIdx.x;
    const int wid  = t >> 5;
    const int lane = t & 31;
    const int g    = lane >> 2;
    const int q    = lane & 3;
    const int mb   = (wid & 3) * 32;  // warp row-block (0,32,64,96)
    const int nbk  = (wid >> 2) * 32; // warp col-block (0,32)
    const int cw   = wid >> 2;
    const uint32_t stage_u32 = (uint32_t)__cvta_generic_to_shared(s.stage);

    // ---- one-time weight staging ----
    for (int i = t; i < 3 * D * D; i += 256) {
        int mat = i >> 12, w = i & 4095;
        int n = w >> 6, k = w & 63;
        const float* W = (mat == 0) ? w2w : (mat == 1) ? a1w : a2w;
        __half h = __float2half_rn(W[k * D + n]);
        if (mat == 0)      s.W2s [n * LDW + k] = h;
        else if (mat == 1) s.A1ts[n * LDW + k] = h;
        else               s.A2s [n * LDW + k] = h;
    }
    for (int i = t; i < D * D; i += 256)
        s.A1Bh[i] = __float2half_rn(a1w[D * D + i]);
    if (t < D) {
        s.a3s[t]  = a3w[t];
        s.b_r2[t] = w2b[t];
        s.b_a1[t] = a1b[t];
        s.b_a2[t] = a2b[t];
    }
    for (int i = t; i < NR * D; i += 256) s.rpre[i] = g_r_pre[i];
    // zero Hbuf/Obuf so garbage f16 rows can never be NaN/inf
    for (int i = t; i < MROWS * LDW / 2; i += 256) {
        ((uint32_t*)s.Hbuf)[i] = 0u;
        ((uint32_t*)s.Obuf)[i] = 0u;
    }
    __syncthreads();

    // ---- register-cached B fragments for GEMM A (W2) and GEMM B (A1t) ----
    uint32_t bcW2[4][8], bcA1[4][8];
    load_bfrag(s.W2s,  bcW2, nbk, lane);
    load_bfrag(s.A1ts, bcA1, nbk, lane);

    // ---- prologue: iter-0 indices ----
    const int nb0 = blockIdx.x * NPI;
    if (t < VROWS) {
        int node = (t >= L_HIST);
        int l = t - L_HIST * node;
        int gi = (nb0 + node) * L_HIST + l;
        s.items[t] = huv[gi];
        s.rats[t]  = hr[gi];
    }
    if (t >= 200 && t < 200 + NPI)
        s.nodesbuf[t - 200] = nodes[nb0 + t - 200];
    __syncthreads();

    // ---- prologue: stage iter-0 h_pre (f16) + uv ----
    for (int c = t; c < VROWS * 8; c += 256) {
        int v = c >> 3, k8 = (c & 7) << 3;
        cp_async16(stage_u32 + (uint32_t)(v * D + k8) * 2,
                   g_h_pre + (size_t)s.items[v] * D + k8);
    }
    asm volatile("cp.async.commit_group;" ::: "memory");
    if (t < NPI * D)
        s.uvs[t] = u2e[(size_t)s.nodesbuf[t >> 6] * D + (t & 63)];
    asm volatile("cp.async.wait_group 0;" ::: "memory");
    __syncthreads();

    for (int nb = nb0; nb < B_NODES; nb += STRIDE) {
        const int nb2 = nb + STRIDE;
        const bool pf = nb2 < B_NODES;

        // ======== phase 0: convert staged f16 rows -> Hbuf ; u_att ========
        {
            const __half2 zero2 = __floats2half2_rn(0.f, 0.f);
            for (int idx = t; idx < VROWS * 8; idx += 256) {
                int vrow = idx >> 3, c8 = (idx & 7) << 3;
                int r = vrow + ((vrow >= L_HIST) ? 14 : 0);   // node*64 + l
                uint2 hv = *(const uint2*)(s.stage + vrow * D + c8);
                uint2 hv2 = *(const uint2*)(s.stage + vrow * D + c8 + 4);
                uint2 rv = *(const uint2*)(s.rpre + s.rats[vrow] * D + c8);
                uint2 rv2 = *(const uint2*)(s.rpre + s.rats[vrow] * D + c8 + 4);
                __half2 o[4];
                o[0] = __hmax2(__hadd2(*(__half2*)&hv.x,  *(__half2*)&rv.x),  zero2);
                o[1] = __hmax2(__hadd2(*(__half2*)&hv.y,  *(__half2*)&rv.y),  zero2);
                o[2] = __hmax2(__hadd2(*(__half2*)&hv2.x, *(__half2*)&rv2.x), zero2);
                o[3] = __hmax2(__hadd2(*(__half2*)&hv2.y, *(__half2*)&rv2.y), zero2);
                *(float4*)(s.Hbuf + r * LDW + c8) = *(float4*)o;
            }
        }
        if (t < NPI * D) {
            int node = t >> 6, j = t & 63;
            float acc0 = s.b_a1[j];
            const float* uv = s.uvs + node * D;
            #pragma unroll 16
            for (int k = 0; k < D; k++)
                acc0 = fmaf(uv[k], __half2float(s.A1Bh[k * D + j]), acc0);
            s.u_att[t] = acc0;
        }
        __syncthreads();

        float acc[2][4][4];

        // ======== phase 1: GEMM A (cached W2) -> Obuf f16 ========
        #pragma unroll
        for (int mt = 0; mt < 2; mt++)
            #pragma unroll
            for (int nt = 0; nt < 4; nt++) {
                int c = nbk + 8 * nt + 2 * q;
                float b0 = s.b_r2[c], b1 = s.b_r2[c + 1];
                acc[mt][nt][0] = b0; acc[mt][nt][1] = b1;
                acc[mt][nt][2] = b0; acc[mt][nt][3] = b1;
            }
        run_mma_gemm128_cb(s.Hbuf, bcW2, acc, mb, lane);
        store_relu_f16_128(s.Obuf, acc, mb, nbk, g, q);
        __syncthreads();

        // ======== phase 2: prefetch idx (regs) ; GEMM B (cached A1t) -> Hbuf ====
        int it2 = 0, rt2 = 0, nd2 = 0;
        if (t < VROWS) {
            int node = (t >= L_HIST);
            int l = t - L_HIST * node;
            int gi = pf ? ((nb2 + node) * L_HIST + l) : 0;
            it2 = huv[gi];
            rt2 = hr[gi];
        }
        if (t >= 200 && t < 200 + NPI)
            nd2 = nodes[pf ? (nb2 + t - 200) : 0];

        #pragma unroll
        for (int mt = 0; mt < 2; mt++) {
            const float* ua = s.u_att + ((mb + 16 * mt) >> 6) * D;
            #pragma unroll
            for (int nt = 0; nt < 4; nt++) {
                int c = nbk + 8 * nt + 2 * q;
                float b0 = ua[c], b1 = ua[c + 1];
                acc[mt][nt][0] = b0; acc[mt][nt][1] = b1;
                acc[mt][nt][2] = b0; acc[mt][nt][3] = b1;
            }
        }
        run_mma_gemm128_cb(s.Obuf, bcA1, acc, mb, lane);
        store_relu_f16_128(s.Hbuf, acc, mb, nbk, g, q);

        if (t < VROWS) { s.items[t] = it2; s.rats[t] = rt2; }
        if (t >= 200 && t < 200 + NPI) s.nodesbuf[t - 200] = nd2;
        __syncthreads();

        // ======== phase 3: cp.async stage(next, f16) ; uv prefetch ; GEMM C ====
        for (int c = t; c < VROWS * 8; c += 256) {
            int v = c >> 3, k8 = (c & 7) << 3;
            cp_async16(stage_u32 + (uint32_t)(v * D + k8) * 2,
                       g_h_pre + (size_t)s.items[v] * D + k8);
        }
        asm volatile("cp.async.commit_group;" ::: "memory");
        float uvreg = 0.f;
        if (t < NPI * D)
            uvreg = u2e[(size_t)s.nodesbuf[t >> 6] * D + (t & 63)];

        #pragma unroll
        for (int mt = 0; mt < 2; mt++)
            #pragma unroll
            for (int nt = 0; nt < 4; nt++) {
                int c = nbk + 8 * nt + 2 * q;
                float b0 = s.b_a2[c], b1 = s.b_a2[c + 1];
                acc[mt][nt][0] = b0; acc[mt][nt][1] = b1;
                acc[mt][nt][2] = b0; acc[mt][nt][3] = b1;
            }
        run_mma_gemm128(s.Hbuf, s.A2s, acc, mb, nbk, lane);
        {
            float p[2][2] = {{0.f, 0.f}, {0.f, 0.f}};
            #pragma unroll
            for (int mt = 0; mt < 2; mt++)
                #pragma unroll
                for (int nt = 0; nt < 4; nt++) {
                    int c = nbk + 8 * nt + 2 * q;
                    float w0 = s.a3s[c], w1 = s.a3s[c + 1];
                    p[mt][0] = fmaf(fmaxf(acc[mt][nt][0], 0.f), w0, p[mt][0]);
                    p[mt][0] = fmaf(fmaxf(acc[mt][nt][1], 0.f), w1, p[mt][0]);
                    p[mt][1] = fmaf(fmaxf(acc[mt][nt][2], 0.f), w0, p[mt][1]);
                    p[mt][1] = fmaf(fmaxf(acc[mt][nt][3], 0.f), w1, p[mt][1]);
                }
            #pragma unroll
            for (int off = 1; off <= 2; off <<= 1) {
                #pragma unroll
                for (int mt = 0; mt < 2; mt++) {
                    p[mt][0] += __shfl_xor_sync(0xffffffffu, p[mt][0], off);
                    p[mt][1] += __shfl_xor_sync(0xffffffffu, p[mt][1], off);
                }
            }
            if (q == 0) {
                #pragma unroll
                for (int mt = 0; mt < 2; mt++) {
                    s.lpart[(mb + 16 * mt + g) * 2 + cw]     = p[mt][0];
                    s.lpart[(mb + 16 * mt + g + 8) * 2 + cw] = p[mt][1];
                }
            }
        }
        __syncthreads();

        // ======== phase 4: softmax (warps 0/1) ; stash uv ========
        if (t < 64) {
            int node = wid;
            int r1 = node * 64 + lane;
            float v1 = s.lpart[r1 * 2] + s.lpart[r1 * 2 + 1];
            float v2 = -1e30f;
            if (lane + 32 < L_HIST)
                v2 = s.lpart[(r1 + 32) * 2] + s.lpart[(r1 + 32) * 2 + 1];
            float m = fmaxf(v1, v2);
            #pragma unroll
            for (int off = 16; off >= 1; off >>= 1)
                m = fmaxf(m, __shfl_xor_sync(0xffffffffu, m, off));
            float e1 = __expf(v1 - m);
            float e2 = (lane + 32 < L_HIST) ? __expf(v2 - m) : 0.f;
            float ssum = e1 + e2;
            #pragma unroll
            for (int off = 16; off >= 1; off >>= 1)
                ssum += __shfl_xor_sync(0xffffffffu, ssum, off);
            float inv = 1.f / ssum;
            s.attw[r1] = e1 * inv;
            if (lane + 32 < L_HIST) s.attw[r1 + 32] = e2 * inv;
        }
        if (t < NPI * D) s.uvs[t] = uvreg;
        __syncthreads();

        // ======== phase 5: out partials (re-read own Obuf f16 tile) ========
        {
            float oc[8] = {0.f, 0.f, 0.f, 0.f, 0.f, 0.f, 0.f, 0.f};
            #pragma unroll
            for (int mt = 0; mt < 2; mt++)
                #pragma unroll
                for (int rr = 0; rr < 2; rr++) {
                    int row = mb + 16 * mt + g + 8 * rr;
                    if ((row & 63) < L_HIST) {     // mask garbage rows
                        float w = s.attw[row];
                        #pragma unroll
                        for (int nt = 0; nt < 4; nt++) {
                            int c = nbk + 8 * nt + 2 * q;
                            float2 ov = __half22float2(
                                *(const __half2*)(s.Obuf + row * LDW + c));
                            oc[2 * nt]     = fmaf(w, ov.x, oc[2 * nt]);
                            oc[2 * nt + 1] = fmaf(w, ov.y, oc[2 * nt + 1]);
                        }
                    }
                }
            #pragma unroll
            for (int off = 4; off <= 16; off <<= 1)
                #pragma unroll
                for (int i = 0; i < 8; i++)
                    oc[i] += __shfl_xor_sync(0xffffffffu, oc[i], off);
            if (g == 0) {
                int basep = (mb >> 5) * D;
                #pragma unroll
                for (int nt = 0; nt < 4; nt++) {
                    s.outp[basep + nbk + 8 * nt + 2 * q]     = oc[2 * nt];
                    s.outp[basep + nbk + 8 * nt + 2 * q + 1] = oc[2 * nt + 1];
                }
            }
        }
        __syncthreads();

        // ======== phase 6: final store ; then wait staged data ========
        if (t < MROWS) {
            int node = t >> 6, j = t & 63;
            out[(size_t)(nb + node) * D + j] =
                s.outp[(node * 2) * D + j] + s.outp[(node * 2 + 1) * D + j];
        }
        asm volatile("cp.async.wait_group 0;" ::: "memory");
        __syncthreads();
    }
}

// ---------------------------------------------------------------------------
extern "C" void kernel_launch(void* const* d_in, const int* in_sizes, int n_in,
                              void* d_out, int out_size)
{
    const int*   nodes = (const int*)d_in[0];
    const int*   huv   = (const int*)d_in[1];
    const int*   hr    = (const int*)d_in[2];
    const float* v2e   = (const float*)d_in[3];
    const float* u2e   = (const float*)d_in[4];
    const float* r2e   = (const float*)d_in[5];
    const float* w1w   = (const float*)d_in[6];
    const float* w1b   = (const float*)d_in[7];
    const float* w2w   = (const float*)d_in[8];
    const float* w2b   = (const float*)d_in[9];
    const float* a1w   = (const float*)d_in[10];
    const float* a1b   = (const float*)d_in[11];
    const float* a2w   = (const float*)d_in[12];
    const float* a2b   = (const float*)d_in[13];
    const float* a3w   = (const float*)d_in[14];
    const float* a3b   = (const float*)d_in[15];
    float* out = (float*)d_out;

    (void)in_sizes; (void)n_in; (void)out_size; (void)a3b;

    cudaFuncSetAttribute(uv_agg_main,
                         cudaFuncAttributeMaxDynamicSharedMemorySize,
                         (int)sizeof(Smem));

    pre_h_kernel<<<(NI + MROWS - 1) / MROWS, 256>>>(v2e, w1w, r2e, w1b);
    uv_agg_main<<<GRID, 256, sizeof(Smem)>>>(nodes, huv, hr, u2e,
                                             w2w, w2b, a1w, a1b,
                                             a2w, a2b, a3w, a3b, out);
}